// round 1
// baseline (speedup 1.0000x reference)
#include <cuda_runtime.h>
#include <math.h>

#define BB   4
#define SS   1024
#define HIDC 768
#define AHC  384
#define HC   6
#define DC   64
#define KSC  9
#define PADC 4
#define MM   (BB*SS)
#define RROWS 4

// ---------------- scratch (no allocation allowed) ----------------
__device__ float g_mq [MM*AHC];
__device__ float g_mk [MM*AHC];
__device__ float g_mv [MM*AHC];
__device__ float g_mkc[MM*AHC];
__device__ float g_co [MM*AHC];
__device__ float g_dw [MM*HIDC];
__device__ float g_ck [MM*HC*KSC];
__device__ float g_tdsm[MM];

// ---------------- reduce helpers (blockDim.x == 256) ----------------
__device__ __forceinline__ float warpSum(float v){
    #pragma unroll
    for (int o=16;o;o>>=1) v += __shfl_xor_sync(0xffffffffu, v, o);
    return v;
}
__device__ __forceinline__ float warpMax(float v){
    #pragma unroll
    for (int o=16;o;o>>=1) v = fmaxf(v, __shfl_xor_sync(0xffffffffu, v, o));
    return v;
}
__device__ __forceinline__ float blockSum256(float v, float* red){
    v = warpSum(v);
    int w = threadIdx.x>>5, l = threadIdx.x&31;
    if (l==0) red[w]=v;
    __syncthreads();
    if (threadIdx.x<32){
        float x = (threadIdx.x<8)? red[threadIdx.x] : 0.f;
        x = warpSum(x);
        if (threadIdx.x==0) red[0]=x;
    }
    __syncthreads();
    float r = red[0];
    __syncthreads();
    return r;
}
__device__ __forceinline__ float blockMax256(float v, float* red){
    v = warpMax(v);
    int w = threadIdx.x>>5, l = threadIdx.x&31;
    if (l==0) red[w]=v;
    __syncthreads();
    if (threadIdx.x<32){
        float x = (threadIdx.x<8)? red[threadIdx.x] : -3e38f;
        x = warpMax(x);
        if (threadIdx.x==0) red[0]=x;
    }
    __syncthreads();
    float r = red[0];
    __syncthreads();
    return r;
}
// exclusive scan over 256 per-thread values; also returns total
__device__ __forceinline__ float blockScanExcl256(float v, float* red, float& total){
    int l = threadIdx.x&31, w = threadIdx.x>>5;
    float x = v;
    #pragma unroll
    for (int o=1;o<32;o<<=1){ float y=__shfl_up_sync(0xffffffffu,x,o); if (l>=o) x+=y; }
    if (l==31) red[w]=x;
    __syncthreads();
    if (threadIdx.x==0){
        float s=0.f;
        #pragma unroll
        for (int k=0;k<8;k++){ float tmp=red[k]; red[k]=s; s+=tmp; }
        red[8]=s;
    }
    __syncthreads();
    float excl = x - v + red[w];
    total = red[8];
    __syncthreads();
    return excl;
}

// ---------------- generic tiled GEMM: C[M,N] = opt(A*A2)[M,K] @ B + bias ----------------
// BT=false: B is [K,N] row-major.  BT=true: B is [N,K] row-major (transposed use).
template<bool BT>
__global__ __launch_bounds__(256) void gemm_kernel(
    const float* __restrict__ A, const float* __restrict__ A2,
    const float* __restrict__ Bm, const float* __restrict__ bias,
    float* __restrict__ C, int M, int N, int K)
{
    __shared__ float As[16][64];
    __shared__ float Bs[16][64];
    int tid  = threadIdx.x;
    int brow = blockIdx.y<<6, bcol = blockIdx.x<<6;
    int tx = tid & 15, ty = tid >> 4;
    float acc[4][4];
    #pragma unroll
    for (int i=0;i<4;i++)
        #pragma unroll
        for (int j=0;j<4;j++) acc[i][j]=0.f;

    int ar = tid>>2, ak = (tid&3)<<2;

    for (int k0=0; k0<K; k0+=16){
        float4 av = *(const float4*)(A + (size_t)(brow+ar)*K + k0+ak);
        if (A2){
            float4 a2 = *(const float4*)(A2 + (size_t)(brow+ar)*K + k0+ak);
            av.x*=a2.x; av.y*=a2.y; av.z*=a2.z; av.w*=a2.w;
        }
        As[ak+0][ar]=av.x; As[ak+1][ar]=av.y; As[ak+2][ar]=av.z; As[ak+3][ar]=av.w;

        if (BT){
            int bc = tid>>2, bk = (tid&3)<<2;
            int gc = bcol + bc;
            float4 bv = make_float4(0.f,0.f,0.f,0.f);
            if (gc < N) bv = *(const float4*)(Bm + (size_t)gc*K + k0 + bk);
            Bs[bk+0][bc]=bv.x; Bs[bk+1][bc]=bv.y; Bs[bk+2][bc]=bv.z; Bs[bk+3][bc]=bv.w;
        } else {
            int bkr = tid>>4, bc4 = (tid&15)<<2;
            int gc = bcol + bc4;
            const float* bp = Bm + (size_t)(k0+bkr)*N + gc;
            Bs[bkr][bc4+0] = (gc+0<N)? bp[0]:0.f;
            Bs[bkr][bc4+1] = (gc+1<N)? bp[1]:0.f;
            Bs[bkr][bc4+2] = (gc+2<N)? bp[2]:0.f;
            Bs[bkr][bc4+3] = (gc+3<N)? bp[3]:0.f;
        }
        __syncthreads();

        #pragma unroll
        for (int kk=0;kk<16;kk++){
            float4 a  = *(const float4*)&As[kk][ty<<2];
            float4 bq = *(const float4*)&Bs[kk][tx<<2];
            float aa[4] = {a.x,a.y,a.z,a.w};
            float bb[4] = {bq.x,bq.y,bq.z,bq.w};
            #pragma unroll
            for (int i=0;i<4;i++)
                #pragma unroll
                for (int j=0;j<4;j++)
                    acc[i][j] = fmaf(aa[i], bb[j], acc[i][j]);
        }
        __syncthreads();
    }

    #pragma unroll
    for (int i=0;i<4;i++){
        int row = brow + (ty<<2) + i;
        #pragma unroll
        for (int j=0;j<4;j++){
            int col = bcol + (tx<<2) + j;
            if (col < N)
                C[(size_t)row*N + col] = acc[i][j] + (bias? bias[col] : 0.f);
        }
    }
}

// ---------------- depthwise conv over sequence ----------------
__global__ __launch_bounds__(HIDC) void dwconv_kernel(
    const float* __restrict__ Kin, const float* __restrict__ dww)
{
    int c = threadIdx.x, s = blockIdx.x, b = blockIdx.y;
    float acc = 0.f;
    #pragma unroll
    for (int k=0;k<KSC;k++){
        int sp = s + k - PADC;
        if (0<=sp && sp<SS)
            acc = fmaf(Kin[((size_t)(b*SS)+sp)*HIDC + c], dww[c*KSC+k], acc);
    }
    g_dw[((size_t)(b*SS)+s)*HIDC + c] = acc;
}

// ---------------- td softmax (per batch, independent of i and h) ----------------
__global__ __launch_bounds__(256) void tdsm_kernel(
    const float* __restrict__ td, const int* __restrict__ mask)
{
    __shared__ float red[9];
    int b = blockIdx.x, t = threadIdx.x;
    float ssum = 0.f;
    for (int j=t;j<SS;j+=256){ float x = td[b*SS+j]; ssum = fmaf(x,x,ssum); }
    float nrm = sqrtf(blockSum256(ssum, red));
    float inv = 1.f / fmaxf(nrm, 1e-12f);
    float lm = -3e38f;
    for (int j=t;j<SS;j+=256)
        if (mask[b*SS+j]) lm = fmaxf(lm, td[b*SS+j]*inv);
    float m = blockMax256(lm, red);
    float ls = 0.f;
    for (int j=t;j<SS;j+=256)
        if (mask[b*SS+j]) ls += expf(td[b*SS+j]*inv - m);
    float Z = blockSum256(ls, red);
    float iz = 1.f / Z;
    for (int j=t;j<SS;j+=256)
        g_tdsm[b*SS+j] = mask[b*SS+j] ? expf(td[b*SS+j]*inv - m)*iz : 0.f;
}

// ---------------- dynamic conv: per-position 9-tap softmax + sliding window ----------------
__global__ __launch_bounds__(AHC) void convout_kernel(float* __restrict__ out)
{
    int t = threadIdx.x, s = blockIdx.x, b = blockIdx.y;
    int h = t >> 6;
    const float* lg = g_ck + ((size_t)(b*SS)+s)*(HC*KSC) + h*KSC;
    float w[KSC]; float mx = -3e38f;
    #pragma unroll
    for (int k=0;k<KSC;k++){ w[k]=lg[k]; mx = fmaxf(mx, w[k]); }
    float sum = 0.f;
    #pragma unroll
    for (int k=0;k<KSC;k++){ w[k]=expf(w[k]-mx); sum += w[k]; }
    float invs = 1.f/sum;
    float a = 0.f;
    #pragma unroll
    for (int k=0;k<KSC;k++){
        int sp = s + k - PADC;
        if (0<=sp && sp<SS)
            a = fmaf(g_co[((size_t)(b*SS)+sp)*AHC + t], w[k], a);
    }
    out[((size_t)(b*SS)+s)*(2*AHC) + AHC + t] = a*invs;
}

// ---------------- attention with distance decay: 4 query rows per block ----------------
__global__ __launch_bounds__(256) void attn_kernel(
    const int* __restrict__ mask, const float* __restrict__ gammas,
    float* __restrict__ out)
{
    __shared__ float sc[RROWS][SS];   // raw scaled scores
    __shared__ float pr[RROWS][SS];   // final probs
    __shared__ float qs[RROWS][DC];
    __shared__ float red[9];
    __shared__ float cred[4][DC];

    int t  = threadIdx.x;
    int i0 = blockIdx.x * RROWS;
    int h  = blockIdx.y;
    int b  = blockIdx.z;

    for (int e=t; e<RROWS*DC; e+=256){
        int r = e>>6, d = e&63;
        qs[r][d] = g_mq[((size_t)(b*SS)+(i0+r))*AHC + h*DC + d];
    }
    __syncthreads();

    int j0 = t*4;
    bool  msk[4]; float tds[4];
    #pragma unroll
    for (int jj=0;jj<4;jj++){
        msk[jj] = mask[b*SS + j0+jj] != 0;
        tds[jj] = g_tdsm[b*SS + j0+jj];
    }

    // ---- scores: each thread owns 4 consecutive keys, 4 rows per block ----
    float acc[4][RROWS];
    #pragma unroll
    for (int jj=0;jj<4;jj++)
        #pragma unroll
        for (int r=0;r<RROWS;r++) acc[jj][r]=0.f;

    const float4* kr0 = (const float4*)(g_mk + ((size_t)(b*SS)+j0)*AHC + h*DC);
    #pragma unroll
    for (int d4=0; d4<16; d4++){
        float q0[RROWS],q1[RROWS],q2[RROWS],q3[RROWS];
        #pragma unroll
        for (int r=0;r<RROWS;r++){
            q0[r]=qs[r][d4*4+0]; q1[r]=qs[r][d4*4+1];
            q2[r]=qs[r][d4*4+2]; q3[r]=qs[r][d4*4+3];
        }
        #pragma unroll
        for (int jj=0;jj<4;jj++){
            float4 kv = kr0[(size_t)jj*(AHC/4) + d4];
            #pragma unroll
            for (int r=0;r<RROWS;r++)
                acc[jj][r] = fmaf(kv.x,q0[r],fmaf(kv.y,q1[r],fmaf(kv.z,q2[r],fmaf(kv.w,q3[r],acc[jj][r]))));
        }
    }
    #pragma unroll
    for (int jj=0;jj<4;jj++)
        #pragma unroll
        for (int r=0;r<RROWS;r++)
            sc[r][j0+jj] = acc[jj][r]*0.125f;

    float ga = gammas[h];
    float gm = -((ga>20.f)? ga : log1pf(expf(ga)));   // gamma = -softplus

    // ---- per-row: softmax, cumsum, distance effect, second softmax ----
    for (int r=0;r<RROWS;r++){
        int i = i0 + r;
        float v[4];
        float lm = -3e38f;
        #pragma unroll
        for (int jj=0;jj<4;jj++){ v[jj]=sc[r][j0+jj]; if (msk[jj]) lm=fmaxf(lm,v[jj]); }
        float m = blockMax256(lm, red);
        float lsum = 0.f;
        #pragma unroll
        for (int jj=0;jj<4;jj++){ v[jj] = msk[jj]? expf(v[jj]-m) : 0.f; lsum += v[jj]; }
        float Z = blockSum256(lsum, red);
        float invZ = 1.f/Z;
        // normalized probs, local inclusive scan
        v[0] = v[0]*invZ;
        v[1] = fmaf(v[1],invZ,v[0]);
        v[2] = fmaf(v[2],invZ,v[1]);
        v[3] = fmaf(v[3],invZ,v[2]);
        float T;
        float off = blockScanExcl256(v[3], red, T);

        float lm2 = -3e38f; float s2v[4];
        #pragma unroll
        for (int jj=0;jj<4;jj++){
            int j = j0+jj;
            float distcum = v[jj] + off;          // inclusive cumsum
            float tail = T - distcum;
            float pos  = fabsf((float)(j - i));
            float ds   = sqrtf(fmaxf(tail*pos, 0.f));
            float te   = expf(gm*ds);
            te = fminf(fmaxf(te, 1e-5f), 1e5f);
            float eff  = te - (j < i ? tds[jj] : 0.f);
            float s2   = sc[r][j]*eff;
            s2v[jj] = s2;
            if (msk[jj]) lm2 = fmaxf(lm2, s2);
        }
        float m2 = blockMax256(lm2, red);
        float ls2 = 0.f;
        #pragma unroll
        for (int jj=0;jj<4;jj++){
            float e = msk[jj]? expf(s2v[jj]-m2) : 0.f;
            s2v[jj] = e; ls2 += e;
        }
        float Z2 = blockSum256(ls2, red);
        float inv2 = 1.f/Z2;
        #pragma unroll
        for (int jj=0;jj<4;jj++) pr[r][j0+jj] = s2v[jj]*inv2;
    }
    __syncthreads();

    // ---- ctx = probs @ V : V rows read once per block ----
    int d = t & 63, gq = t >> 6;
    float cacc[RROWS] = {0.f,0.f,0.f,0.f};
    for (int j=gq; j<SS; j+=4){
        float mvv = g_mv[((size_t)(b*SS)+j)*AHC + h*DC + d];
        #pragma unroll
        for (int r=0;r<RROWS;r++) cacc[r] = fmaf(pr[r][j], mvv, cacc[r]);
    }
    for (int r=0;r<RROWS;r++){
        cred[gq][d] = cacc[r];
        __syncthreads();
        if (t < 64){
            float s = cred[0][t]+cred[1][t]+cred[2][t]+cred[3][t];
            out[((size_t)(b*SS)+(i0+r))*(2*AHC) + h*DC + t] = s;
        }
        __syncthreads();
    }
}

// ---------------- launch ----------------
extern "C" void kernel_launch(void* const* d_in, const int* in_sizes, int n_in,
                              void* d_out, int out_size)
{
    const float* Q     = (const float*)d_in[0];
    const float* Kin   = (const float*)d_in[1];
    const float* V     = (const float*)d_in[2];
    const float* td    = (const float*)d_in[3];
    const int*   mask  = (const int*)  d_in[4];
    const float* Wq    = (const float*)d_in[5];
    const float* Wk    = (const float*)d_in[6];
    const float* Wv    = (const float*)d_in[7];
    const float* dw_w  = (const float*)d_in[8];
    const float* pw_w  = (const float*)d_in[9];
    const float* sep_b = (const float*)d_in[10];
    const float* ck_W  = (const float*)d_in[11];
    const float* ck_b  = (const float*)d_in[12];
    const float* co_W  = (const float*)d_in[13];
    const float* co_b  = (const float*)d_in[14];
    const float* gam   = (const float*)d_in[15];
    float* out = (float*)d_out;

    float *mq,*mk,*mv,*mkc,*co,*dw,*ck;
    cudaGetSymbolAddress((void**)&mq,  g_mq);
    cudaGetSymbolAddress((void**)&mk,  g_mk);
    cudaGetSymbolAddress((void**)&mv,  g_mv);
    cudaGetSymbolAddress((void**)&mkc, g_mkc);
    cudaGetSymbolAddress((void**)&co,  g_co);
    cudaGetSymbolAddress((void**)&dw,  g_dw);
    cudaGetSymbolAddress((void**)&ck,  g_ck);

    dim3 gproj(AHC/64, MM/64);   // 6 x 64
    gemm_kernel<false><<<gproj,256>>>(Q,   nullptr, Wq,   nullptr, mq,  MM, AHC, HIDC);
    gemm_kernel<false><<<gproj,256>>>(Kin, nullptr, Wk,   nullptr, mk,  MM, AHC, HIDC);
    gemm_kernel<false><<<gproj,256>>>(V,   nullptr, Wv,   nullptr, mv,  MM, AHC, HIDC);
    gemm_kernel<false><<<gproj,256>>>(V,   nullptr, co_W, co_b,    co,  MM, AHC, HIDC);

    dwconv_kernel<<<dim3(SS,BB), HIDC>>>(Kin, dw_w);
    gemm_kernel<true><<<gproj,256>>>(dw, nullptr, pw_w, sep_b, mkc, MM, AHC, HIDC);

    // conv_attn = mkc * mq fused into A-load; N = H*KS = 54
    dim3 gck((HC*KSC+63)/64, MM/64);
    gemm_kernel<false><<<gck,256>>>(mkc, mq, ck_W, ck_b, ck, MM, HC*KSC, AHC);

    tdsm_kernel<<<BB,256>>>(td, mask);
    convout_kernel<<<dim3(SS,BB), AHC>>>(out);
    attn_kernel<<<dim3(SS/RROWS, HC, BB), 256>>>(mask, gam, out);
}

// round 3
// speedup vs baseline: 1.2461x; 1.2461x over previous
#include <cuda_runtime.h>
#include <math.h>

#define BB   4
#define SS   1024
#define HIDC 768
#define AHC  384
#define HC   6
#define DC   64
#define KSC  9
#define PADC 4
#define MM   (BB*SS)
#define R8   8

// ---------------- scratch ----------------
__device__ float g_mq [MM*AHC];
__device__ float g_mk [MM*AHC];
__device__ float g_mv [MM*AHC];
__device__ float g_mkc[MM*AHC];
__device__ float g_co [MM*AHC];
__device__ float g_dw [MM*HIDC];
__device__ float g_ck [MM*HC*KSC];
__device__ float g_tdsm[MM];

// ---------------- fast math (FMA/ALU only, no MUFU) ----------------
__device__ __forceinline__ float fexp(float x){
    float z = x * 1.44269504f;
    z = fmaxf(z, -120.f);
    float zi = rintf(z);
    float f  = z - zi;
    float p  = 1.3333558e-3f;
    p = fmaf(p, f, 9.6181291e-3f);
    p = fmaf(p, f, 5.5504109e-2f);
    p = fmaf(p, f, 2.4022651e-1f);
    p = fmaf(p, f, 6.9314718e-1f);
    p = fmaf(p, f, 1.0f);
    int e = (int)zi;
    float s = __int_as_float((e + 127) << 23);
    return s * p;
}
__device__ __forceinline__ float fsqrt(float x){
    x = fmaxf(x, 1e-12f);
    float y = __int_as_float(0x5f3759dfu - (__float_as_int(x) >> 1));
    y = y * fmaf(-0.5f*x*y, y, 1.5f);
    y = y * fmaf(-0.5f*x*y, y, 1.5f);
    return x * y;
}

// ---------------- warp helpers ----------------
__device__ __forceinline__ float warpSum(float v){
    #pragma unroll
    for (int o=16;o;o>>=1) v += __shfl_xor_sync(0xffffffffu, v, o);
    return v;
}
__device__ __forceinline__ float warpMax(float v){
    #pragma unroll
    for (int o=16;o;o>>=1) v = fmaxf(v, __shfl_xor_sync(0xffffffffu, v, o));
    return v;
}
__device__ __forceinline__ float blockSum256(float v, float* red){
    v = warpSum(v);
    int w = threadIdx.x>>5, l = threadIdx.x&31;
    if (l==0) red[w]=v;
    __syncthreads();
    if (threadIdx.x<32){
        float x = (threadIdx.x<8)? red[threadIdx.x] : 0.f;
        x = warpSum(x);
        if (threadIdx.x==0) red[0]=x;
    }
    __syncthreads();
    float r = red[0];
    __syncthreads();
    return r;
}
__device__ __forceinline__ float blockMax256(float v, float* red){
    v = warpMax(v);
    int w = threadIdx.x>>5, l = threadIdx.x&31;
    if (l==0) red[w]=v;
    __syncthreads();
    if (threadIdx.x<32){
        float x = (threadIdx.x<8)? red[threadIdx.x] : -3e38f;
        x = warpMax(x);
        if (threadIdx.x==0) red[0]=x;
    }
    __syncthreads();
    float r = red[0];
    __syncthreads();
    return r;
}

// ---------------- big merged GEMM: 4096 x 384 x 768, 5 ops ----------------
// z=0: mq=Q@Wq  z=1: mk=K@Wk  z=2: mv=V@Wv  z=3: co=V@coW+cob
// z=4: mkc = dw @ pw_w^T + sepb   (B transposed: [N,K])
#define BM 128
#define BN 128
#define BK 16
#define LDA (BM+4)

__global__ __launch_bounds__(256) void big_gemm(
   const float* __restrict__ Q, const float* __restrict__ Kin, const float* __restrict__ V,
   const float* __restrict__ Wq, const float* __restrict__ Wk, const float* __restrict__ Wv,
   const float* __restrict__ coW, const float* __restrict__ cob,
   const float* __restrict__ pww, const float* __restrict__ sepb)
{
    __shared__ float As[2][BK][LDA];
    __shared__ float Bs[2][BK][LDA];

    int z = blockIdx.z;
    const float* A; const float* B; float* C; const float* bias = nullptr; bool bt = false;
    switch (z){
      case 0: A=Q;    B=Wq;  C=g_mq;  break;
      case 1: A=Kin;  B=Wk;  C=g_mk;  break;
      case 2: A=V;    B=Wv;  C=g_mv;  break;
      case 3: A=V;    B=coW; C=g_co;  bias=cob;  break;
      default:A=g_dw; B=pww; C=g_mkc; bias=sepb; bt=true; break;
    }

    const int tid  = threadIdx.x;
    const int brow = blockIdx.y*BM, bcol = blockIdx.x*BN;
    const int tx = tid & 15, ty = tid >> 4;

    // A-load indices: 512 float4 needed; thread covers (ra,kqa) and (ra+64,kqa)
    const int ra  = tid >> 2, kqa = (tid & 3) << 2;
    // B normal: (kb, n4b) and (kb+8, n4b)
    const int kb  = tid >> 5, n4b = (tid & 31) << 2;
    // B transposed: (nb, kqa) and (nb+64, kqa)
    const int nb  = tid >> 2;

    float4 pa0, pa1, pb0, pb1;

    // prime tile 0
    {
        pa0 = *(const float4*)(A + (size_t)(brow+ra   )*HIDC + kqa);
        pa1 = *(const float4*)(A + (size_t)(brow+ra+64)*HIDC + kqa);
        if (bt){
            pb0 = *(const float4*)(B + (size_t)(bcol+nb   )*HIDC + kqa);
            pb1 = *(const float4*)(B + (size_t)(bcol+nb+64)*HIDC + kqa);
        } else {
            pb0 = *(const float4*)(B + (size_t)(kb  )*AHC + bcol + n4b);
            pb1 = *(const float4*)(B + (size_t)(kb+8)*AHC + bcol + n4b);
        }
        As[0][kqa+0][ra]=pa0.x; As[0][kqa+1][ra]=pa0.y; As[0][kqa+2][ra]=pa0.z; As[0][kqa+3][ra]=pa0.w;
        As[0][kqa+0][ra+64]=pa1.x; As[0][kqa+1][ra+64]=pa1.y; As[0][kqa+2][ra+64]=pa1.z; As[0][kqa+3][ra+64]=pa1.w;
        if (bt){
            Bs[0][kqa+0][nb]=pb0.x; Bs[0][kqa+1][nb]=pb0.y; Bs[0][kqa+2][nb]=pb0.z; Bs[0][kqa+3][nb]=pb0.w;
            Bs[0][kqa+0][nb+64]=pb1.x; Bs[0][kqa+1][nb+64]=pb1.y; Bs[0][kqa+2][nb+64]=pb1.z; Bs[0][kqa+3][nb+64]=pb1.w;
        } else {
            *(float4*)&Bs[0][kb  ][n4b] = pb0;
            *(float4*)&Bs[0][kb+8][n4b] = pb1;
        }
    }
    __syncthreads();

    float acc[8][8];
    #pragma unroll
    for (int i=0;i<8;i++)
        #pragma unroll
        for (int j=0;j<8;j++) acc[i][j]=0.f;

    const int nt = HIDC/BK;   // 48
    int buf = 0;
    for (int t0=0; t0<nt; t0++){
        if (t0+1 < nt){
            int k0 = (t0+1)*BK;
            pa0 = *(const float4*)(A + (size_t)(brow+ra   )*HIDC + k0 + kqa);
            pa1 = *(const float4*)(A + (size_t)(brow+ra+64)*HIDC + k0 + kqa);
            if (bt){
                pb0 = *(const float4*)(B + (size_t)(bcol+nb   )*HIDC + k0 + kqa);
                pb1 = *(const float4*)(B + (size_t)(bcol+nb+64)*HIDC + k0 + kqa);
            } else {
                pb0 = *(const float4*)(B + (size_t)(k0+kb  )*AHC + bcol + n4b);
                pb1 = *(const float4*)(B + (size_t)(k0+kb+8)*AHC + bcol + n4b);
            }
        }
        #pragma unroll
        for (int k=0;k<BK;k++){
            float4 a0 = *(const float4*)&As[buf][k][ty*8];
            float4 a1 = *(const float4*)&As[buf][k][ty*8+4];
            float4 b0 = *(const float4*)&Bs[buf][k][tx*8];
            float4 b1 = *(const float4*)&Bs[buf][k][tx*8+4];
            float aa[8] = {a0.x,a0.y,a0.z,a0.w,a1.x,a1.y,a1.z,a1.w};
            float bb[8] = {b0.x,b0.y,b0.z,b0.w,b1.x,b1.y,b1.z,b1.w};
            #pragma unroll
            for (int i=0;i<8;i++)
                #pragma unroll
                for (int j=0;j<8;j++)
                    acc[i][j] = fmaf(aa[i], bb[j], acc[i][j]);
        }
        if (t0+1 < nt){
            int nb2 = buf^1;
            As[nb2][kqa+0][ra]=pa0.x; As[nb2][kqa+1][ra]=pa0.y; As[nb2][kqa+2][ra]=pa0.z; As[nb2][kqa+3][ra]=pa0.w;
            As[nb2][kqa+0][ra+64]=pa1.x; As[nb2][kqa+1][ra+64]=pa1.y; As[nb2][kqa+2][ra+64]=pa1.z; As[nb2][kqa+3][ra+64]=pa1.w;
            if (bt){
                Bs[nb2][kqa+0][nb]=pb0.x; Bs[nb2][kqa+1][nb]=pb0.y; Bs[nb2][kqa+2][nb]=pb0.z; Bs[nb2][kqa+3][nb]=pb0.w;
                Bs[nb2][kqa+0][nb+64]=pb1.x; Bs[nb2][kqa+1][nb+64]=pb1.y; Bs[nb2][kqa+2][nb+64]=pb1.z; Bs[nb2][kqa+3][nb+64]=pb1.w;
            } else {
                *(float4*)&Bs[nb2][kb  ][n4b] = pb0;
                *(float4*)&Bs[nb2][kb+8][n4b] = pb1;
            }
            __syncthreads();
            buf ^= 1;
        }
    }

    float bv[8];
    #pragma unroll
    for (int j=0;j<8;j++) bv[j] = bias ? bias[bcol + tx*8 + j] : 0.f;
    #pragma unroll
    for (int i=0;i<8;i++){
        size_t row = brow + ty*8 + i;
        float4 o0 = make_float4(acc[i][0]+bv[0], acc[i][1]+bv[1], acc[i][2]+bv[2], acc[i][3]+bv[3]);
        float4 o1 = make_float4(acc[i][4]+bv[4], acc[i][5]+bv[5], acc[i][6]+bv[6], acc[i][7]+bv[7]);
        *(float4*)&C[row*AHC + bcol + tx*8    ] = o0;
        *(float4*)&C[row*AHC + bcol + tx*8 + 4] = o1;
    }
}

// ---------------- small generic GEMM for ck (N=54, K=384) ----------------
__global__ __launch_bounds__(256) void gemm_small(
    const float* __restrict__ A, const float* __restrict__ A2,
    const float* __restrict__ Bm, const float* __restrict__ bias,
    float* __restrict__ C, int M, int N, int K)
{
    __shared__ float As[16][64];
    __shared__ float Bs[16][64];
    int tid  = threadIdx.x;
    int brow = blockIdx.y<<6, bcol = blockIdx.x<<6;
    int tx = tid & 15, ty = tid >> 4;
    float acc[4][4];
    #pragma unroll
    for (int i=0;i<4;i++)
        #pragma unroll
        for (int j=0;j<4;j++) acc[i][j]=0.f;

    int ar = tid>>2, ak = (tid&3)<<2;
    for (int k0=0; k0<K; k0+=16){
        float4 av = *(const float4*)(A + (size_t)(brow+ar)*K + k0+ak);
        float4 a2 = *(const float4*)(A2 + (size_t)(brow+ar)*K + k0+ak);
        av.x*=a2.x; av.y*=a2.y; av.z*=a2.z; av.w*=a2.w;
        As[ak+0][ar]=av.x; As[ak+1][ar]=av.y; As[ak+2][ar]=av.z; As[ak+3][ar]=av.w;

        int bkr = tid>>4, bc4 = (tid&15)<<2;
        int gc = bcol + bc4;
        const float* bp = Bm + (size_t)(k0+bkr)*N + gc;
        Bs[bkr][bc4+0] = (gc+0<N)? bp[0]:0.f;
        Bs[bkr][bc4+1] = (gc+1<N)? bp[1]:0.f;
        Bs[bkr][bc4+2] = (gc+2<N)? bp[2]:0.f;
        Bs[bkr][bc4+3] = (gc+3<N)? bp[3]:0.f;
        __syncthreads();

        #pragma unroll
        for (int kk=0;kk<16;kk++){
            float4 a  = *(const float4*)&As[kk][ty<<2];
            float4 bq = *(const float4*)&Bs[kk][tx<<2];
            float aa[4] = {a.x,a.y,a.z,a.w};
            float bb[4] = {bq.x,bq.y,bq.z,bq.w};
            #pragma unroll
            for (int i=0;i<4;i++)
                #pragma unroll
                for (int j=0;j<4;j++)
                    acc[i][j] = fmaf(aa[i], bb[j], acc[i][j]);
        }
        __syncthreads();
    }
    #pragma unroll
    for (int i=0;i<4;i++){
        int row = brow + (ty<<2) + i;
        #pragma unroll
        for (int j=0;j<4;j++){
            int col = bcol + (tx<<2) + j;
            if (col < N)
                C[(size_t)row*N + col] = acc[i][j] + (bias? bias[col] : 0.f);
        }
    }
}

// ---------------- depthwise conv over sequence ----------------
__global__ __launch_bounds__(HIDC) void dwconv_kernel(
    const float* __restrict__ Kin, const float* __restrict__ dww)
{
    int c = threadIdx.x, s = blockIdx.x, b = blockIdx.y;
    float acc = 0.f;
    #pragma unroll
    for (int k=0;k<KSC;k++){
        int sp = s + k - PADC;
        if (0<=sp && sp<SS)
            acc = fmaf(Kin[((size_t)(b*SS)+sp)*HIDC + c], dww[c*KSC+k], acc);
    }
    g_dw[((size_t)(b*SS)+s)*HIDC + c] = acc;
}

// ---------------- td softmax ----------------
__global__ __launch_bounds__(256) void tdsm_kernel(
    const float* __restrict__ td, const int* __restrict__ mask)
{
    __shared__ float red[9];
    int b = blockIdx.x, t = threadIdx.x;
    float ssum = 0.f;
    for (int j=t;j<SS;j+=256){ float x = td[b*SS+j]; ssum = fmaf(x,x,ssum); }
    float nrm = sqrtf(blockSum256(ssum, red));
    float inv = 1.f / fmaxf(nrm, 1e-12f);
    float lm = -3e38f;
    for (int j=t;j<SS;j+=256)
        if (mask[b*SS+j]) lm = fmaxf(lm, td[b*SS+j]*inv);
    float m = blockMax256(lm, red);
    float ls = 0.f;
    for (int j=t;j<SS;j+=256)
        if (mask[b*SS+j]) ls += expf(td[b*SS+j]*inv - m);
    float Z = blockSum256(ls, red);
    float iz = 1.f / Z;
    for (int j=t;j<SS;j+=256)
        g_tdsm[b*SS+j] = mask[b*SS+j] ? expf(td[b*SS+j]*inv - m)*iz : 0.f;
}

// ---------------- dynamic conv out ----------------
__global__ __launch_bounds__(AHC) void convout_kernel(float* __restrict__ out)
{
    int t = threadIdx.x, s = blockIdx.x, b = blockIdx.y;
    int h = t >> 6;
    const float* lg = g_ck + ((size_t)(b*SS)+s)*(HC*KSC) + h*KSC;
    float w[KSC]; float mx = -3e38f;
    #pragma unroll
    for (int k=0;k<KSC;k++){ w[k]=lg[k]; mx = fmaxf(mx, w[k]); }
    float sum = 0.f;
    #pragma unroll
    for (int k=0;k<KSC;k++){ w[k]=fexp(w[k]-mx); sum += w[k]; }
    float invs = 1.f/sum;
    float a = 0.f;
    #pragma unroll
    for (int k=0;k<KSC;k++){
        int sp = s + k - PADC;
        if (0<=sp && sp<SS)
            a = fmaf(g_co[((size_t)(b*SS)+sp)*AHC + t], w[k], a);
    }
    out[((size_t)(b*SS)+s)*(2*AHC) + AHC + t] = a*invs;
}

// ---------------- attention: 8 rows/block, warp-per-row softmax ----------------
#define JM(j) ((j) + ((j)>>5))
__global__ __launch_bounds__(256) void attn_kernel(
    const int* __restrict__ mask, const float* __restrict__ gammas,
    float* __restrict__ out)
{
    __shared__ float sc[R8][SS + SS/32];  // padded scores -> probs in place
    __shared__ float qs[R8][DC];
    __shared__ float tdsmS[SS];
    __shared__ float maskS[SS];
    __shared__ float cred[4][DC];

    const int t    = threadIdx.x;
    const int warp = t >> 5, lane = t & 31;
    const int i0 = blockIdx.x * R8;
    const int h  = blockIdx.y;
    const int b  = blockIdx.z;

    for (int e=t; e<R8*DC; e+=256){
        int r = e>>6, d = e&63;
        qs[r][d] = g_mq[((size_t)(b*SS)+(i0+r))*AHC + h*DC + d];
    }
    for (int e=t; e<SS; e+=256){
        maskS[e] = mask[b*SS+e] ? 1.f : 0.f;
        tdsmS[e] = g_tdsm[b*SS+e];
    }
    __syncthreads();

    // ---- phase 1: scores. thread owns 4 consecutive keys, 8 rows ----
    {
        const int j0 = t*4;
        float acc[4][R8];
        #pragma unroll
        for (int jj=0;jj<4;jj++)
            #pragma unroll
            for (int r=0;r<R8;r++) acc[jj][r]=0.f;

        const float4* kr0 = (const float4*)(g_mk + ((size_t)(b*SS)+j0)*AHC + h*DC);
        #pragma unroll
        for (int d4=0; d4<16; d4++){
            float4 kv[4];
            #pragma unroll
            for (int jj=0;jj<4;jj++) kv[jj] = kr0[(size_t)jj*(AHC/4) + d4];
            #pragma unroll
            for (int r=0;r<R8;r++){
                float4 q = *(const float4*)&qs[r][d4*4];
                #pragma unroll
                for (int jj=0;jj<4;jj++)
                    acc[jj][r] = fmaf(kv[jj].x,q.x,fmaf(kv[jj].y,q.y,fmaf(kv[jj].z,q.z,fmaf(kv[jj].w,q.w,acc[jj][r]))));
            }
        }
        #pragma unroll
        for (int jj=0;jj<4;jj++)
            #pragma unroll
            for (int r=0;r<R8;r++)
                sc[r][JM(j0+jj)] = acc[jj][r]*0.125f;
    }
    __syncthreads();

    // ---- phase 2: one warp per row ----
    {
        const int i  = i0 + warp;
        const int jb = lane*32;
        float gv = gammas[h];
        float gm = -((gv > 20.f)? gv : log1pf(expf(gv)));

        float v[32];
        float lm = -3e38f;
        #pragma unroll
        for (int c=0;c<32;c++){
            int j = jb+c;
            float s = sc[warp][JM(j)];
            v[c] = s;
            if (maskS[j] != 0.f) lm = fmaxf(lm, s);
        }
        lm = warpMax(lm);
        float lsum = 0.f;
        #pragma unroll
        for (int c=0;c<32;c++){
            float e = (maskS[jb+c] != 0.f)? fexp(v[c]-lm) : 0.f;
            v[c] = e; lsum += e;
        }
        float Z = warpSum(lsum);
        float invZ = 1.f / Z;
        float run = 0.f;
        #pragma unroll
        for (int c=0;c<32;c++){ run = fmaf(v[c], invZ, run); v[c] = run; }
        // warp exclusive scan of lane totals
        float xs = run;
        #pragma unroll
        for (int o=1;o<32;o<<=1){ float y=__shfl_up_sync(0xffffffffu,xs,o); if (lane>=o) xs+=y; }
        float T   = __shfl_sync(0xffffffffu, xs, 31);
        float off = xs - run;

        float lm2 = -3e38f;
        #pragma unroll
        for (int c=0;c<32;c++){
            int j = jb+c;
            float distcum = v[c] + off;
            float tail = T - distcum;
            float pos  = fabsf((float)(j - i));
            float ds   = fsqrt(tail*pos);
            float te   = fexp(gm*ds);
            te = fminf(fmaxf(te, 1e-5f), 1e5f);
            float eff = te - ((j < i)? tdsmS[j] : 0.f);
            float s2 = sc[warp][JM(j)] * eff;
            v[c] = s2;
            if (maskS[j] != 0.f) lm2 = fmaxf(lm2, s2);
        }
        lm2 = warpMax(lm2);
        float ls2 = 0.f;
        #pragma unroll
        for (int c=0;c<32;c++){
            float e = (maskS[jb+c] != 0.f)? fexp(v[c]-lm2) : 0.f;
            v[c] = e; ls2 += e;
        }
        float Z2 = warpSum(ls2);
        float inv2 = 1.f / Z2;
        #pragma unroll
        for (int c=0;c<32;c++)
            sc[warp][JM(jb+c)] = v[c]*inv2;
    }
    __syncthreads();

    // ---- phase 3: ctx = probs @ V ----
    {
        const int d = t & 63, gq = t >> 6;
        float cacc[R8];
        #pragma unroll
        for (int r=0;r<R8;r++) cacc[r]=0.f;
        const float* vbase = g_mv + ((size_t)(b*SS))*AHC + h*DC + d;
        for (int j = gq; j < SS; j += 16){
            float m0 = vbase[(size_t)(j    )*AHC];
            float m1 = vbase[(size_t)(j+ 4 )*AHC];
            float m2 = vbase[(size_t)(j+ 8 )*AHC];
            float m3 = vbase[(size_t)(j+12 )*AHC];
            #pragma unroll
            for (int r=0;r<R8;r++){
                cacc[r] = fmaf(sc[r][JM(j    )], m0, cacc[r]);
                cacc[r] = fmaf(sc[r][JM(j+ 4 )], m1, cacc[r]);
                cacc[r] = fmaf(sc[r][JM(j+ 8 )], m2, cacc[r]);
                cacc[r] = fmaf(sc[r][JM(j+12 )], m3, cacc[r]);
            }
        }
        #pragma unroll
        for (int r=0;r<R8;r++){
            __syncthreads();
            cred[gq][d] = cacc[r];
            __syncthreads();
            if (t < 64){
                float sv = cred[0][t]+cred[1][t]+cred[2][t]+cred[3][t];
                out[((size_t)(b*SS)+(i0+r))*(2*AHC) + h*DC + t] = sv;
            }
        }
    }
}

// ---------------- launch ----------------
extern "C" void kernel_launch(void* const* d_in, const int* in_sizes, int n_in,
                              void* d_out, int out_size)
{
    const float* Q     = (const float*)d_in[0];
    const float* Kin   = (const float*)d_in[1];
    const float* V     = (const float*)d_in[2];
    const float* td    = (const float*)d_in[3];
    const int*   mask  = (const int*)  d_in[4];
    const float* Wq    = (const float*)d_in[5];
    const float* Wk    = (const float*)d_in[6];
    const float* Wv    = (const float*)d_in[7];
    const float* dw_w  = (const float*)d_in[8];
    const float* pw_w  = (const float*)d_in[9];
    const float* sep_b = (const float*)d_in[10];
    const float* ck_W  = (const float*)d_in[11];
    const float* ck_b  = (const float*)d_in[12];
    const float* co_W  = (const float*)d_in[13];
    const float* co_b  = (const float*)d_in[14];
    const float* gam   = (const float*)d_in[15];
    float* out = (float*)d_out;

    float *mq,*mkc,*ck;
    cudaGetSymbolAddress((void**)&mq,  g_mq);
    cudaGetSymbolAddress((void**)&mkc, g_mkc);
    cudaGetSymbolAddress((void**)&ck,  g_ck);

    dwconv_kernel<<<dim3(SS,BB), HIDC>>>(Kin, dw_w);

    dim3 gbig(AHC/BN, MM/BM, 5);   // 3 x 32 x 5 = 480 blocks
    big_gemm<<<gbig, 256>>>(Q, Kin, V, Wq, Wk, Wv, co_W, co_b, pw_w, sep_b);

    dim3 gck((HC*KSC+63)/64, MM/64);
    gemm_small<<<gck, 256>>>(mkc, mq, ck_W, ck_b, ck, MM, HC*KSC, AHC);

    tdsm_kernel<<<BB,256>>>(td, mask);
    convout_kernel<<<dim3(SS,BB), AHC>>>(out);
    attn_kernel<<<dim3(SS/R8, HC, BB), 256>>>(mask, gam, out);
}

// round 9
// speedup vs baseline: 1.3677x; 1.0976x over previous
#include <cuda_runtime.h>
#include <mma.h>
#include <math.h>

using namespace nvcuda;

#define BB   4
#define SS   1024
#define HIDC 768
#define AHC  384
#define HC   6
#define DC   64
#define KSC  9
#define PADC 4
#define MM   (BB*SS)
#define R8   8
#define CKN  (HC*KSC)   // 54

// ---------------- scratch ----------------
__device__ float g_mq [MM*AHC];
__device__ float g_mk [MM*AHC];
__device__ float g_mv [MM*AHC];
__device__ float g_mkc[MM*AHC];
__device__ float g_co [MM*AHC];
__device__ float g_dw [MM*HIDC];
__device__ float g_ck [MM*CKN];
__device__ float g_tdsm[MM];

// ---------------- fast math (FMA/ALU only, no MUFU) ----------------
__device__ __forceinline__ float fexp(float x){
    float z = x * 1.44269504f;
    z = fmaxf(z, -120.f);
    float zi = rintf(z);
    float f  = z - zi;
    float p  = 1.3333558e-3f;
    p = fmaf(p, f, 9.6181291e-3f);
    p = fmaf(p, f, 5.5504109e-2f);
    p = fmaf(p, f, 2.4022651e-1f);
    p = fmaf(p, f, 6.9314718e-1f);
    p = fmaf(p, f, 1.0f);
    int e = (int)zi;
    float s = __int_as_float((e + 127) << 23);
    return s * p;
}
__device__ __forceinline__ float fsqrt(float x){
    x = fmaxf(x, 1e-12f);
    float y = __int_as_float(0x5f3759dfu - (__float_as_int(x) >> 1));
    y = y * fmaf(-0.5f*x*y, y, 1.5f);
    y = y * fmaf(-0.5f*x*y, y, 1.5f);
    return x * y;
}

// ---------------- warp helpers ----------------
__device__ __forceinline__ float warpSum(float v){
    #pragma unroll
    for (int o=16;o;o>>=1) v += __shfl_xor_sync(0xffffffffu, v, o);
    return v;
}
__device__ __forceinline__ float warpMax(float v){
    #pragma unroll
    for (int o=16;o;o>>=1) v = fmaxf(v, __shfl_xor_sync(0xffffffffu, v, o));
    return v;
}
__device__ __forceinline__ float blockSum256(float v, float* red){
    v = warpSum(v);
    int w = threadIdx.x>>5, l = threadIdx.x&31;
    if (l==0) red[w]=v;
    __syncthreads();
    if (threadIdx.x<32){
        float x = (threadIdx.x<8)? red[threadIdx.x] : 0.f;
        x = warpSum(x);
        if (threadIdx.x==0) red[0]=x;
    }
    __syncthreads();
    float r = red[0];
    __syncthreads();
    return r;
}
__device__ __forceinline__ float blockMax256(float v, float* red){
    v = warpMax(v);
    int w = threadIdx.x>>5, l = threadIdx.x&31;
    if (l==0) red[w]=v;
    __syncthreads();
    if (threadIdx.x<32){
        float x = (threadIdx.x<8)? red[threadIdx.x] : -3e38f;
        x = warpMax(x);
        if (threadIdx.x==0) red[0]=x;
    }
    __syncthreads();
    float r = red[0];
    __syncthreads();
    return r;
}

// ================= WMMA tf32 GEMM =================
#define BM 128
#define BN 128
#define BK 16
#define LDA (BK+8)    // 24, multiple of 4
#define LDB (BN+4)    // 132, multiple of 4

typedef wmma::fragment<wmma::matrix_a, 16,16,8, wmma::precision::tf32, wmma::row_major> FragA;
typedef wmma::fragment<wmma::matrix_b, 16,16,8, wmma::precision::tf32, wmma::row_major> FragB;
typedef wmma::fragment<wmma::accumulator, 16,16,8, float> FragC;

__device__ __forceinline__ void cvtA(FragA& f){
    #pragma unroll
    for (int i=0;i<f.num_elements;i++) f.x[i] = wmma::__float_to_tf32(f.x[i]);
}
__device__ __forceinline__ void cvtB(FragB& f){
    #pragma unroll
    for (int i=0;i<f.num_elements;i++) f.x[i] = wmma::__float_to_tf32(f.x[i]);
}

// ---------------- merged 5-way projection GEMM (wmma tf32) ----------------
// z=0: mq=Q@Wq  z=1: mk=K@Wk  z=2: mv=V@Wv  z=3: co=V@coW+cob
// z=4: mkc = dw @ pw_w^T + sepb  (B is [N,K])
__global__ __launch_bounds__(256) void big_gemm_tc(
   const float* __restrict__ Q, const float* __restrict__ Kin, const float* __restrict__ V,
   const float* __restrict__ Wq, const float* __restrict__ Wk, const float* __restrict__ Wv,
   const float* __restrict__ coW, const float* __restrict__ cob,
   const float* __restrict__ pww, const float* __restrict__ sepb)
{
    __shared__ __align__(16) float As[2][BM][LDA];
    __shared__ __align__(16) float Bs[2][BK][LDB];

    int z = blockIdx.z;
    const float* A; const float* B; float* C; const float* bias = nullptr; bool bt = false;
    switch (z){
      case 0: A=Q;    B=Wq;  C=g_mq;  break;
      case 1: A=Kin;  B=Wk;  C=g_mk;  break;
      case 2: A=V;    B=Wv;  C=g_mv;  break;
      case 3: A=V;    B=coW; C=g_co;  bias=cob;  break;
      default:A=g_dw; B=pww; C=g_mkc; bias=sepb; bt=true; break;
    }

    const int tid = threadIdx.x;
    const int warp = tid>>5;
    const int brow = blockIdx.y*BM, bcol = blockIdx.x*BN;
    const int wm = warp>>2, wn = warp&3;     // 2 x 4 warp grid
    const int m0 = wm*64, n0 = wn*32;

    const int ar = tid>>2, ac = (tid&3)<<2;   // A: rows ar, ar+64
    const int bk = tid>>4, bn = (tid&15)<<2;  // B normal: cols bn, bn+64
    const int tn = tid>>2, tk = (tid&3)<<2;   // B transposed

    float4 pa0, pa1, pb0, pb1;

    auto ldtile = [&](int k0){
        pa0 = *(const float4*)(A + (size_t)(brow+ar   )*HIDC + k0 + ac);
        pa1 = *(const float4*)(A + (size_t)(brow+ar+64)*HIDC + k0 + ac);
        if (bt){
            pb0 = *(const float4*)(B + (size_t)(bcol+tn   )*HIDC + k0 + tk);
            pb1 = *(const float4*)(B + (size_t)(bcol+tn+64)*HIDC + k0 + tk);
        } else {
            pb0 = *(const float4*)(B + (size_t)(k0+bk)*AHC + bcol + bn);
            pb1 = *(const float4*)(B + (size_t)(k0+bk)*AHC + bcol + bn + 64);
        }
    };
    auto sttile = [&](int buf){
        *(float4*)&As[buf][ar   ][ac] = pa0;
        *(float4*)&As[buf][ar+64][ac] = pa1;
        if (bt){
            Bs[buf][tk+0][tn] = pb0.x; Bs[buf][tk+1][tn] = pb0.y;
            Bs[buf][tk+2][tn] = pb0.z; Bs[buf][tk+3][tn] = pb0.w;
            Bs[buf][tk+0][tn+64] = pb1.x; Bs[buf][tk+1][tn+64] = pb1.y;
            Bs[buf][tk+2][tn+64] = pb1.z; Bs[buf][tk+3][tn+64] = pb1.w;
        } else {
            *(float4*)&Bs[buf][bk][bn   ] = pb0;
            *(float4*)&Bs[buf][bk][bn+64] = pb1;
        }
    };

    FragC acc[4][2];
    #pragma unroll
    for (int mt=0;mt<4;mt++)
        #pragma unroll
        for (int nt=0;nt<2;nt++)
            wmma::fill_fragment(acc[mt][nt], 0.f);

    ldtile(0); sttile(0); __syncthreads();
    const int NT = HIDC/BK;   // 48
    int buf = 0;
    for (int t=0;t<NT;t++){
        if (t+1<NT) ldtile((t+1)*BK);
        #pragma unroll
        for (int ks=0;ks<2;ks++){
            FragA af[4]; FragB bf[2];
            #pragma unroll
            for (int mt=0;mt<4;mt++){
                wmma::load_matrix_sync(af[mt], &As[buf][m0+mt*16][ks*8], LDA);
                cvtA(af[mt]);
            }
            #pragma unroll
            for (int nt=0;nt<2;nt++){
                wmma::load_matrix_sync(bf[nt], &Bs[buf][ks*8][n0+nt*16], LDB);
                cvtB(bf[nt]);
            }
            #pragma unroll
            for (int mt=0;mt<4;mt++)
                #pragma unroll
                for (int nt=0;nt<2;nt++)
                    wmma::mma_sync(acc[mt][nt], af[mt], bf[nt], acc[mt][nt]);
        }
        if (t+1<NT){
            sttile(buf^1);
            __syncthreads();
            buf ^= 1;
        }
    }

    if (!bias){
        #pragma unroll
        for (int mt=0;mt<4;mt++)
            #pragma unroll
            for (int nt=0;nt<2;nt++)
                wmma::store_matrix_sync(
                    C + (size_t)(brow+m0+mt*16)*AHC + bcol + n0 + nt*16,
                    acc[mt][nt], AHC, wmma::mem_row_major);
    } else {
        // staged epilogue with bias add; per-warp 16x20 patch in As
        __syncthreads();
        float* stage = &As[0][0][0] + warp*(16*20);
        const int lane = tid&31;
        #pragma unroll
        for (int mt=0;mt<4;mt++)
            #pragma unroll
            for (int nt=0;nt<2;nt++){
                wmma::store_matrix_sync(stage, acc[mt][nt], 20, wmma::mem_row_major);
                __syncwarp();
                #pragma unroll
                for (int e=lane; e<256; e+=32){
                    int r = e>>4, c = e&15;
                    int row = brow + m0 + mt*16 + r;
                    int col = bcol + n0 + nt*16 + c;
                    C[(size_t)row*AHC + col] = stage[r*20+c] + bias[col];
                }
                __syncwarp();
            }
    }
}

// ---------------- ck GEMM: (mkc*mq)[4096x384] @ ck_W[384x54] + ck_b ----------------
#define LDB2 68
__global__ __launch_bounds__(256) void ck_gemm_tc(
    const float* __restrict__ ckW, const float* __restrict__ ckb)
{
    __shared__ __align__(16) float As[2][BM][LDA];
    __shared__ __align__(16) float Bs[2][BK][LDB2];

    const float* A  = g_mkc;
    const float* A2 = g_mq;
    const int K = AHC, N = CKN;

    const int tid = threadIdx.x;
    const int warp = tid>>5;
    const int brow = blockIdx.y*BM;
    const int wm = warp>>1, wn = warp&1;     // 4 x 2 warp grid: warp tile 32x32
    const int m0 = wm*32, n0 = wn*32;

    const int ar = tid>>2, ac = (tid&3)<<2;
    const int bk = tid>>4, bcn = (tid&15)<<2;   // B element block (bk, bcn..bcn+3)

    float4 pa0, pa1;
    float  pb[4];

    auto ldtile = [&](int k0){
        pa0 = *(const float4*)(A  + (size_t)(brow+ar   )*K + k0 + ac);
        float4 q0 = *(const float4*)(A2 + (size_t)(brow+ar   )*K + k0 + ac);
        pa0.x*=q0.x; pa0.y*=q0.y; pa0.z*=q0.z; pa0.w*=q0.w;
        pa1 = *(const float4*)(A  + (size_t)(brow+ar+64)*K + k0 + ac);
        float4 q1 = *(const float4*)(A2 + (size_t)(brow+ar+64)*K + k0 + ac);
        pa1.x*=q1.x; pa1.y*=q1.y; pa1.z*=q1.z; pa1.w*=q1.w;
        const float* bp = ckW + (size_t)(k0+bk)*N;
        #pragma unroll
        for (int e=0;e<4;e++){
            int c = bcn+e;
            pb[e] = (c<N)? bp[c] : 0.f;
        }
    };
    auto sttile = [&](int buf){
        *(float4*)&As[buf][ar   ][ac] = pa0;
        *(float4*)&As[buf][ar+64][ac] = pa1;
        #pragma unroll
        for (int e=0;e<4;e++) Bs[buf][bk][bcn+e] = pb[e];
    };

    FragC acc[2][2];
    #pragma unroll
    for (int mt=0;mt<2;mt++)
        #pragma unroll
        for (int nt=0;nt<2;nt++)
            wmma::fill_fragment(acc[mt][nt], 0.f);

    ldtile(0); sttile(0); __syncthreads();
    const int NT = K/BK;   // 24
    int buf = 0;
    for (int t=0;t<NT;t++){
        if (t+1<NT) ldtile((t+1)*BK);
        #pragma unroll
        for (int ks=0;ks<2;ks++){
            FragA af[2]; FragB bf[2];
            #pragma unroll
            for (int mt=0;mt<2;mt++){
                wmma::load_matrix_sync(af[mt], &As[buf][m0+mt*16][ks*8], LDA);
                cvtA(af[mt]);
            }
            #pragma unroll
            for (int nt=0;nt<2;nt++){
                wmma::load_matrix_sync(bf[nt], &Bs[buf][ks*8][n0+nt*16], LDB2);
                cvtB(bf[nt]);
            }
            #pragma unroll
            for (int mt=0;mt<2;mt++)
                #pragma unroll
                for (int nt=0;nt<2;nt++)
                    wmma::mma_sync(acc[mt][nt], af[mt], bf[nt], acc[mt][nt]);
        }
        if (t+1<NT){
            sttile(buf^1);
            __syncthreads();
            buf ^= 1;
        }
    }

    // staged epilogue: bias + col<54 guard
    __syncthreads();
    float* stage = &As[0][0][0] + warp*(16*20);
    const int lane = tid&31;
    #pragma unroll
    for (int mt=0;mt<2;mt++)
        #pragma unroll
        for (int nt=0;nt<2;nt++){
            wmma::store_matrix_sync(stage, acc[mt][nt], 20, wmma::mem_row_major);
            __syncwarp();
            #pragma unroll
            for (int e=lane; e<256; e+=32){
                int r = e>>4, c = e&15;
                int row = brow + m0 + mt*16 + r;
                int col = n0 + nt*16 + c;
                if (col < N)
                    g_ck[(size_t)row*N + col] = stage[r*20+c] + ckb[col];
            }
            __syncwarp();
        }
}

// ---------------- depthwise conv over sequence ----------------
__global__ __launch_bounds__(HIDC) void dwconv_kernel(
    const float* __restrict__ Kin, const float* __restrict__ dww)
{
    int c = threadIdx.x, s = blockIdx.x, b = blockIdx.y;
    float acc = 0.f;
    #pragma unroll
    for (int k=0;k<KSC;k++){
        int sp = s + k - PADC;
        if (0<=sp && sp<SS)
            acc = fmaf(Kin[((size_t)(b*SS)+sp)*HIDC + c], dww[c*KSC+k], acc);
    }
    g_dw[((size_t)(b*SS)+s)*HIDC + c] = acc;
}

// ---------------- td softmax ----------------
__global__ __launch_bounds__(256) void tdsm_kernel(
    const float* __restrict__ td, const int* __restrict__ mask)
{
    __shared__ float red[9];
    int b = blockIdx.x, t = threadIdx.x;
    float ssum = 0.f;
    for (int j=t;j<SS;j+=256){ float x = td[b*SS+j]; ssum = fmaf(x,x,ssum); }
    float nrm = sqrtf(blockSum256(ssum, red));
    float inv = 1.f / fmaxf(nrm, 1e-12f);
    float lm = -3e38f;
    for (int j=t;j<SS;j+=256)
        if (mask[b*SS+j]) lm = fmaxf(lm, td[b*SS+j]*inv);
    float m = blockMax256(lm, red);
    float ls = 0.f;
    for (int j=t;j<SS;j+=256)
        if (mask[b*SS+j]) ls += expf(td[b*SS+j]*inv - m);
    float Z = blockSum256(ls, red);
    float iz = 1.f / Z;
    for (int j=t;j<SS;j+=256)
        g_tdsm[b*SS+j] = mask[b*SS+j] ? expf(td[b*SS+j]*inv - m)*iz : 0.f;
}

// ---------------- dynamic conv out ----------------
__global__ __launch_bounds__(AHC) void convout_kernel(float* __restrict__ out)
{
    int t = threadIdx.x, s = blockIdx.x, b = blockIdx.y;
    int h = t >> 6;
    const float* lg = g_ck + ((size_t)(b*SS)+s)*CKN + h*KSC;
    float w[KSC]; float mx = -3e38f;
    #pragma unroll
    for (int k=0;k<KSC;k++){ w[k]=lg[k]; mx = fmaxf(mx, w[k]); }
    float sum = 0.f;
    #pragma unroll
    for (int k=0;k<KSC;k++){ w[k]=fexp(w[k]-mx); sum += w[k]; }
    float invs = 1.f/sum;
    float a = 0.f;
    #pragma unroll
    for (int k=0;k<KSC;k++){
        int sp = s + k - PADC;
        if (0<=sp && sp<SS)
            a = fmaf(g_co[((size_t)(b*SS)+sp)*AHC + t], w[k], a);
    }
    out[((size_t)(b*SS)+s)*(2*AHC) + AHC + t] = a*invs;
}

// ---------------- attention: 8 rows/block, warp-per-row softmax ----------------
#define JM(j) ((j) + ((j)>>5))
__global__ __launch_bounds__(256) void attn_kernel(
    const int* __restrict__ mask, const float* __restrict__ gammas,
    float* __restrict__ out)
{
    __shared__ float sc[R8][SS + SS/32];
    __shared__ float qs[R8][DC];
    __shared__ float tdsmS[SS];
    __shared__ float maskS[SS];
    __shared__ float cred[4][DC];

    const int t    = threadIdx.x;
    const int warp = t >> 5, lane = t & 31;
    const int i0 = blockIdx.x * R8;
    const int h  = blockIdx.y;
    const int b  = blockIdx.z;

    for (int e=t; e<R8*DC; e+=256){
        int r = e>>6, d = e&63;
        qs[r][d] = g_mq[((size_t)(b*SS)+(i0+r))*AHC + h*DC + d];
    }
    for (int e=t; e<SS; e+=256){
        maskS[e] = mask[b*SS+e] ? 1.f : 0.f;
        tdsmS[e] = g_tdsm[b*SS+e];
    }
    __syncthreads();

    {
        const int j0 = t*4;
        float acc[4][R8];
        #pragma unroll
        for (int jj=0;jj<4;jj++)
            #pragma unroll
            for (int r=0;r<R8;r++) acc[jj][r]=0.f;

        const float4* kr0 = (const float4*)(g_mk + ((size_t)(b*SS)+j0)*AHC + h*DC);
        #pragma unroll
        for (int d4=0; d4<16; d4++){
            float4 kv[4];
            #pragma unroll
            for (int jj=0;jj<4;jj++) kv[jj] = kr0[(size_t)jj*(AHC/4) + d4];
            #pragma unroll
            for (int r=0;r<R8;r++){
                float4 q = *(const float4*)&qs[r][d4*4];
                #pragma unroll
                for (int jj=0;jj<4;jj++)
                    acc[jj][r] = fmaf(kv[jj].x,q.x,fmaf(kv[jj].y,q.y,fmaf(kv[jj].z,q.z,fmaf(kv[jj].w,q.w,acc[jj][r]))));
            }
        }
        #pragma unroll
        for (int jj=0;jj<4;jj++)
            #pragma unroll
            for (int r=0;r<R8;r++)
                sc[r][JM(j0+jj)] = acc[jj][r]*0.125f;
    }
    __syncthreads();

    {
        const int i  = i0 + warp;
        const int jb = lane*32;
        float gv = gammas[h];
        float gm = -((gv > 20.f)? gv : log1pf(expf(gv)));

        float v[32];
        float lm = -3e38f;
        #pragma unroll
        for (int c=0;c<32;c++){
            int j = jb+c;
            float s = sc[warp][JM(j)];
            v[c] = s;
            if (maskS[j] != 0.f) lm = fmaxf(lm, s);
        }
        lm = warpMax(lm);
        float lsum = 0.f;
        #pragma unroll
        for (int c=0;c<32;c++){
            float e = (maskS[jb+c] != 0.f)? fexp(v[c]-lm) : 0.f;
            v[c] = e; lsum += e;
        }
        float Z = warpSum(lsum);
        float invZ = 1.f / Z;
        float run = 0.f;
        #pragma unroll
        for (int c=0;c<32;c++){ run = fmaf(v[c], invZ, run); v[c] = run; }
        float xs = run;
        #pragma unroll
        for (int o=1;o<32;o<<=1){ float y=__shfl_up_sync(0xffffffffu,xs,o); if (lane>=o) xs+=y; }
        float T   = __shfl_sync(0xffffffffu, xs, 31);
        float off = xs - run;

        float lm2 = -3e38f;
        #pragma unroll
        for (int c=0;c<32;c++){
            int j = jb+c;
            float distcum = v[c] + off;
            float tail = T - distcum;
            float pos  = fabsf((float)(j - i));
            float ds   = fsqrt(tail*pos);
            float te   = fexp(gm*ds);
            te = fminf(fmaxf(te, 1e-5f), 1e5f);
            float eff = te - ((j < i)? tdsmS[j] : 0.f);
            float s2 = sc[warp][JM(j)] * eff;
            v[c] = s2;
            if (maskS[j] != 0.f) lm2 = fmaxf(lm2, s2);
        }
        lm2 = warpMax(lm2);
        float ls2 = 0.f;
        #pragma unroll
        for (int c=0;c<32;c++){
            float e = (maskS[jb+c] != 0.f)? fexp(v[c]-lm2) : 0.f;
            v[c] = e; ls2 += e;
        }
        float Z2 = warpSum(ls2);
        float inv2 = 1.f / Z2;
        #pragma unroll
        for (int c=0;c<32;c++)
            sc[warp][JM(jb+c)] = v[c]*inv2;
    }
    __syncthreads();

    {
        const int d = t & 63, gq = t >> 6;
        float cacc[R8];
        #pragma unroll
        for (int r=0;r<R8;r++) cacc[r]=0.f;
        const float* vbase = g_mv + ((size_t)(b*SS))*AHC + h*DC + d;
        for (int j = gq; j < SS; j += 16){
            float m0 = vbase[(size_t)(j    )*AHC];
            float m1 = vbase[(size_t)(j+ 4 )*AHC];
            float m2 = vbase[(size_t)(j+ 8 )*AHC];
            float m3 = vbase[(size_t)(j+12 )*AHC];
            #pragma unroll
            for (int r=0;r<R8;r++){
                cacc[r] = fmaf(sc[r][JM(j    )], m0, cacc[r]);
                cacc[r] = fmaf(sc[r][JM(j+ 4 )], m1, cacc[r]);
                cacc[r] = fmaf(sc[r][JM(j+ 8 )], m2, cacc[r]);
                cacc[r] = fmaf(sc[r][JM(j+12 )], m3, cacc[r]);
            }
        }
        #pragma unroll
        for (int r=0;r<R8;r++){
            __syncthreads();
            cred[gq][d] = cacc[r];
            __syncthreads();
            if (t < 64){
                float sv = cred[0][t]+cred[1][t]+cred[2][t]+cred[3][t];
                out[((size_t)(b*SS)+(i0+r))*(2*AHC) + h*DC + t] = sv;
            }
        }
    }
}

// ---------------- launch ----------------
extern "C" void kernel_launch(void* const* d_in, const int* in_sizes, int n_in,
                              void* d_out, int out_size)
{
    const float* Q     = (const float*)d_in[0];
    const float* Kin   = (const float*)d_in[1];
    const float* V     = (const float*)d_in[2];
    const float* td    = (const float*)d_in[3];
    const int*   mask  = (const int*)  d_in[4];
    const float* Wq    = (const float*)d_in[5];
    const float* Wk    = (const float*)d_in[6];
    const float* Wv    = (const float*)d_in[7];
    const float* dw_w  = (const float*)d_in[8];
    const float* pw_w  = (const float*)d_in[9];
    const float* sep_b = (const float*)d_in[10];
    const float* ck_W  = (const float*)d_in[11];
    const float* ck_b  = (const float*)d_in[12];
    const float* co_W  = (const float*)d_in[13];
    const float* co_b  = (const float*)d_in[14];
    const float* gam   = (const float*)d_in[15];
    float* out = (float*)d_out;

    dwconv_kernel<<<dim3(SS,BB), HIDC>>>(Kin, dw_w);

    dim3 gbig(AHC/BN, MM/BM, 5);   // 3 x 32 x 5 = 480 blocks
    big_gemm_tc<<<gbig, 256>>>(Q, Kin, V, Wq, Wk, Wv, co_W, co_b, pw_w, sep_b);

    dim3 gck(1, MM/BM);
    ck_gemm_tc<<<gck, 256>>>(ck_W, ck_b);

    tdsm_kernel<<<BB,256>>>(td, mask);
    convout_kernel<<<dim3(SS,BB), AHC>>>(out);
    attn_kernel<<<dim3(SS/R8, HC, BB), 256>>>(mask, gam, out);
}

// round 11
// speedup vs baseline: 1.8267x; 1.3356x over previous
#include <cuda_runtime.h>
#include <mma.h>
#include <math.h>

using namespace nvcuda;

#define BB   4
#define SS   1024
#define HIDC 768
#define AHC  384
#define HC   6
#define DC   64
#define KSC  9
#define PADC 4
#define MM   (BB*SS)
#define CKN  (HC*KSC)   // 54
#define AR   16         // attention rows per block
#define SCL  1040       // score row leading dim (mult of 4)

// ---------------- scratch ----------------
__device__ float g_mq [MM*AHC];
__device__ float g_mk [MM*AHC];
__device__ float g_mv [MM*AHC];
__device__ float g_mkc[MM*AHC];
__device__ float g_co [MM*AHC];
__device__ float g_dw [MM*HIDC];
__device__ float g_ck [MM*CKN];
__device__ float g_tdsm[MM];

// ---------------- fast math (FMA/ALU only, no MUFU) ----------------
__device__ __forceinline__ float fexp(float x){
    float z = x * 1.44269504f;
    z = fmaxf(z, -120.f);
    float zi = rintf(z);
    float f  = z - zi;
    float p  = 1.3333558e-3f;
    p = fmaf(p, f, 9.6181291e-3f);
    p = fmaf(p, f, 5.5504109e-2f);
    p = fmaf(p, f, 2.4022651e-1f);
    p = fmaf(p, f, 6.9314718e-1f);
    p = fmaf(p, f, 1.0f);
    int e = (int)zi;
    float s = __int_as_float((e + 127) << 23);
    return s * p;
}
__device__ __forceinline__ float fsqrt(float x){
    x = fmaxf(x, 1e-12f);
    float y = __int_as_float(0x5f3759dfu - (__float_as_int(x) >> 1));
    y = y * fmaf(-0.5f*x*y, y, 1.5f);
    y = y * fmaf(-0.5f*x*y, y, 1.5f);
    return x * y;
}

// ---------------- warp helpers ----------------
__device__ __forceinline__ float warpSum(float v){
    #pragma unroll
    for (int o=16;o;o>>=1) v += __shfl_xor_sync(0xffffffffu, v, o);
    return v;
}
__device__ __forceinline__ float warpMax(float v){
    #pragma unroll
    for (int o=16;o;o>>=1) v = fmaxf(v, __shfl_xor_sync(0xffffffffu, v, o));
    return v;
}
__device__ __forceinline__ float blockSum256(float v, float* red){
    v = warpSum(v);
    int w = threadIdx.x>>5, l = threadIdx.x&31;
    if (l==0) red[w]=v;
    __syncthreads();
    if (threadIdx.x<32){
        float x = (threadIdx.x<8)? red[threadIdx.x] : 0.f;
        x = warpSum(x);
        if (threadIdx.x==0) red[0]=x;
    }
    __syncthreads();
    float r = red[0];
    __syncthreads();
    return r;
}
__device__ __forceinline__ float blockMax256(float v, float* red){
    v = warpMax(v);
    int w = threadIdx.x>>5, l = threadIdx.x&31;
    if (l==0) red[w]=v;
    __syncthreads();
    if (threadIdx.x<32){
        float x = (threadIdx.x<8)? red[threadIdx.x] : -3e38f;
        x = warpMax(x);
        if (threadIdx.x==0) red[0]=x;
    }
    __syncthreads();
    float r = red[0];
    __syncthreads();
    return r;
}

// ================= WMMA tf32 GEMM =================
#define BM 128
#define BN 128
#define BK 16
#define LDA (BK+8)    // 24
#define LDB (BN+4)    // 132

typedef wmma::fragment<wmma::matrix_a, 16,16,8, wmma::precision::tf32, wmma::row_major> FragA;
typedef wmma::fragment<wmma::matrix_b, 16,16,8, wmma::precision::tf32, wmma::row_major> FragB;
typedef wmma::fragment<wmma::matrix_b, 16,16,8, wmma::precision::tf32, wmma::col_major> FragBc;
typedef wmma::fragment<wmma::accumulator, 16,16,8, float> FragC;

__device__ __forceinline__ void cvtA(FragA& f){
    #pragma unroll
    for (int i=0;i<f.num_elements;i++) f.x[i] = wmma::__float_to_tf32(f.x[i]);
}
__device__ __forceinline__ void cvtB(FragB& f){
    #pragma unroll
    for (int i=0;i<f.num_elements;i++) f.x[i] = wmma::__float_to_tf32(f.x[i]);
}

// ---------------- merged 5-way projection GEMM (wmma tf32) ----------------
__global__ __launch_bounds__(256) void big_gemm_tc(
   const float* __restrict__ Q, const float* __restrict__ Kin, const float* __restrict__ V,
   const float* __restrict__ Wq, const float* __restrict__ Wk, const float* __restrict__ Wv,
   const float* __restrict__ coW, const float* __restrict__ cob,
   const float* __restrict__ pww, const float* __restrict__ sepb)
{
    __shared__ __align__(16) float As[2][BM][LDA];
    __shared__ __align__(16) float Bs[2][BK][LDB];

    int z = blockIdx.z;
    const float* A; const float* B; float* C; const float* bias = nullptr; bool bt = false;
    switch (z){
      case 0: A=Q;    B=Wq;  C=g_mq;  break;
      case 1: A=Kin;  B=Wk;  C=g_mk;  break;
      case 2: A=V;    B=Wv;  C=g_mv;  break;
      case 3: A=V;    B=coW; C=g_co;  bias=cob;  break;
      default:A=g_dw; B=pww; C=g_mkc; bias=sepb; bt=true; break;
    }

    const int tid = threadIdx.x;
    const int warp = tid>>5;
    const int brow = blockIdx.y*BM, bcol = blockIdx.x*BN;
    const int wm = warp>>2, wn = warp&3;
    const int m0 = wm*64, n0 = wn*32;

    const int ar = tid>>2, ac = (tid&3)<<2;
    const int bk = tid>>4, bn = (tid&15)<<2;
    const int tn = tid>>2, tk = (tid&3)<<2;

    float4 pa0, pa1, pb0, pb1;

    auto ldtile = [&](int k0){
        pa0 = *(const float4*)(A + (size_t)(brow+ar   )*HIDC + k0 + ac);
        pa1 = *(const float4*)(A + (size_t)(brow+ar+64)*HIDC + k0 + ac);
        if (bt){
            pb0 = *(const float4*)(B + (size_t)(bcol+tn   )*HIDC + k0 + tk);
            pb1 = *(const float4*)(B + (size_t)(bcol+tn+64)*HIDC + k0 + tk);
        } else {
            pb0 = *(const float4*)(B + (size_t)(k0+bk)*AHC + bcol + bn);
            pb1 = *(const float4*)(B + (size_t)(k0+bk)*AHC + bcol + bn + 64);
        }
    };
    auto sttile = [&](int buf){
        *(float4*)&As[buf][ar   ][ac] = pa0;
        *(float4*)&As[buf][ar+64][ac] = pa1;
        if (bt){
            Bs[buf][tk+0][tn] = pb0.x; Bs[buf][tk+1][tn] = pb0.y;
            Bs[buf][tk+2][tn] = pb0.z; Bs[buf][tk+3][tn] = pb0.w;
            Bs[buf][tk+0][tn+64] = pb1.x; Bs[buf][tk+1][tn+64] = pb1.y;
            Bs[buf][tk+2][tn+64] = pb1.z; Bs[buf][tk+3][tn+64] = pb1.w;
        } else {
            *(float4*)&Bs[buf][bk][bn   ] = pb0;
            *(float4*)&Bs[buf][bk][bn+64] = pb1;
        }
    };

    FragC acc[4][2];
    #pragma unroll
    for (int mt=0;mt<4;mt++)
        #pragma unroll
        for (int nt=0;nt<2;nt++)
            wmma::fill_fragment(acc[mt][nt], 0.f);

    ldtile(0); sttile(0); __syncthreads();
    const int NT = HIDC/BK;
    int buf = 0;
    for (int t=0;t<NT;t++){
        if (t+1<NT) ldtile((t+1)*BK);
        #pragma unroll
        for (int ks=0;ks<2;ks++){
            FragA af[4]; FragB bf[2];
            #pragma unroll
            for (int mt=0;mt<4;mt++){
                wmma::load_matrix_sync(af[mt], &As[buf][m0+mt*16][ks*8], LDA);
                cvtA(af[mt]);
            }
            #pragma unroll
            for (int nt=0;nt<2;nt++){
                wmma::load_matrix_sync(bf[nt], &Bs[buf][ks*8][n0+nt*16], LDB);
                cvtB(bf[nt]);
            }
            #pragma unroll
            for (int mt=0;mt<4;mt++)
                #pragma unroll
                for (int nt=0;nt<2;nt++)
                    wmma::mma_sync(acc[mt][nt], af[mt], bf[nt], acc[mt][nt]);
        }
        if (t+1<NT){
            sttile(buf^1);
            __syncthreads();
            buf ^= 1;
        }
    }

    if (!bias){
        #pragma unroll
        for (int mt=0;mt<4;mt++)
            #pragma unroll
            for (int nt=0;nt<2;nt++)
                wmma::store_matrix_sync(
                    C + (size_t)(brow+m0+mt*16)*AHC + bcol + n0 + nt*16,
                    acc[mt][nt], AHC, wmma::mem_row_major);
    } else {
        __syncthreads();
        float* stage = &As[0][0][0] + warp*(16*20);
        const int lane = tid&31;
        #pragma unroll
        for (int mt=0;mt<4;mt++)
            #pragma unroll
            for (int nt=0;nt<2;nt++){
                wmma::store_matrix_sync(stage, acc[mt][nt], 20, wmma::mem_row_major);
                __syncwarp();
                #pragma unroll
                for (int e=lane; e<256; e+=32){
                    int r = e>>4, c = e&15;
                    int row = brow + m0 + mt*16 + r;
                    int col = bcol + n0 + nt*16 + c;
                    C[(size_t)row*AHC + col] = stage[r*20+c] + bias[col];
                }
                __syncwarp();
            }
    }
}

// ---------------- ck GEMM: (mkc*mq)[4096x384] @ ck_W[384x54] + ck_b ----------------
#define LDB2 68
__global__ __launch_bounds__(256) void ck_gemm_tc(
    const float* __restrict__ ckW, const float* __restrict__ ckb)
{
    __shared__ __align__(16) float As[2][BM][LDA];
    __shared__ __align__(16) float Bs[2][BK][LDB2];

    const float* A  = g_mkc;
    const float* A2 = g_mq;
    const int K = AHC, N = CKN;

    const int tid = threadIdx.x;
    const int warp = tid>>5;
    const int brow = blockIdx.y*BM;
    const int wm = warp>>1, wn = warp&1;
    const int m0 = wm*32, n0 = wn*32;

    const int ar = tid>>2, ac = (tid&3)<<2;
    const int bk = tid>>4, bcn = (tid&15)<<2;

    float4 pa0, pa1;
    float  pb[4];

    auto ldtile = [&](int k0){
        pa0 = *(const float4*)(A  + (size_t)(brow+ar   )*K + k0 + ac);
        float4 q0 = *(const float4*)(A2 + (size_t)(brow+ar   )*K + k0 + ac);
        pa0.x*=q0.x; pa0.y*=q0.y; pa0.z*=q0.z; pa0.w*=q0.w;
        pa1 = *(const float4*)(A  + (size_t)(brow+ar+64)*K + k0 + ac);
        float4 q1 = *(const float4*)(A2 + (size_t)(brow+ar+64)*K + k0 + ac);
        pa1.x*=q1.x; pa1.y*=q1.y; pa1.z*=q1.z; pa1.w*=q1.w;
        const float* bp = ckW + (size_t)(k0+bk)*N;
        #pragma unroll
        for (int e=0;e<4;e++){
            int c = bcn+e;
            pb[e] = (c<N)? bp[c] : 0.f;
        }
    };
    auto sttile = [&](int buf){
        *(float4*)&As[buf][ar   ][ac] = pa0;
        *(float4*)&As[buf][ar+64][ac] = pa1;
        #pragma unroll
        for (int e=0;e<4;e++) Bs[buf][bk][bcn+e] = pb[e];
    };

    FragC acc[2][2];
    #pragma unroll
    for (int mt=0;mt<2;mt++)
        #pragma unroll
        for (int nt=0;nt<2;nt++)
            wmma::fill_fragment(acc[mt][nt], 0.f);

    ldtile(0); sttile(0); __syncthreads();
    const int NT = K/BK;
    int buf = 0;
    for (int t=0;t<NT;t++){
        if (t+1<NT) ldtile((t+1)*BK);
        #pragma unroll
        for (int ks=0;ks<2;ks++){
            FragA af[2]; FragB bf[2];
            #pragma unroll
            for (int mt=0;mt<2;mt++){
                wmma::load_matrix_sync(af[mt], &As[buf][m0+mt*16][ks*8], LDA);
                cvtA(af[mt]);
            }
            #pragma unroll
            for (int nt=0;nt<2;nt++){
                wmma::load_matrix_sync(bf[nt], &Bs[buf][ks*8][n0+nt*16], LDB2);
                cvtB(bf[nt]);
            }
            #pragma unroll
            for (int mt=0;mt<2;mt++)
                #pragma unroll
                for (int nt=0;nt<2;nt++)
                    wmma::mma_sync(acc[mt][nt], af[mt], bf[nt], acc[mt][nt]);
        }
        if (t+1<NT){
            sttile(buf^1);
            __syncthreads();
            buf ^= 1;
        }
    }

    __syncthreads();
    float* stage = &As[0][0][0] + warp*(16*20);
    const int lane = tid&31;
    #pragma unroll
    for (int mt=0;mt<2;mt++)
        #pragma unroll
        for (int nt=0;nt<2;nt++){
            wmma::store_matrix_sync(stage, acc[mt][nt], 20, wmma::mem_row_major);
            __syncwarp();
            #pragma unroll
            for (int e=lane; e<256; e+=32){
                int r = e>>4, c = e&15;
                int row = brow + m0 + mt*16 + r;
                int col = n0 + nt*16 + c;
                if (col < N)
                    g_ck[(size_t)row*N + col] = stage[r*20+c] + ckb[col];
            }
            __syncwarp();
        }
}

// ---------------- depthwise conv over sequence ----------------
__global__ __launch_bounds__(HIDC) void dwconv_kernel(
    const float* __restrict__ Kin, const float* __restrict__ dww)
{
    int c = threadIdx.x, s = blockIdx.x, b = blockIdx.y;
    float acc = 0.f;
    #pragma unroll
    for (int k=0;k<KSC;k++){
        int sp = s + k - PADC;
        if (0<=sp && sp<SS)
            acc = fmaf(Kin[((size_t)(b*SS)+sp)*HIDC + c], dww[c*KSC+k], acc);
    }
    g_dw[((size_t)(b*SS)+s)*HIDC + c] = acc;
}

// ---------------- td softmax ----------------
__global__ __launch_bounds__(256) void tdsm_kernel(
    const float* __restrict__ td, const int* __restrict__ mask)
{
    __shared__ float red[9];
    int b = blockIdx.x, t = threadIdx.x;
    float ssum = 0.f;
    for (int j=t;j<SS;j+=256){ float x = td[b*SS+j]; ssum = fmaf(x,x,ssum); }
    float nrm = sqrtf(blockSum256(ssum, red));
    float inv = 1.f / fmaxf(nrm, 1e-12f);
    float lm = -3e38f;
    for (int j=t;j<SS;j+=256)
        if (mask[b*SS+j]) lm = fmaxf(lm, td[b*SS+j]*inv);
    float m = blockMax256(lm, red);
    float ls = 0.f;
    for (int j=t;j<SS;j+=256)
        if (mask[b*SS+j]) ls += expf(td[b*SS+j]*inv - m);
    float Z = blockSum256(ls, red);
    float iz = 1.f / Z;
    for (int j=t;j<SS;j+=256)
        g_tdsm[b*SS+j] = mask[b*SS+j] ? expf(td[b*SS+j]*inv - m)*iz : 0.f;
}

// ---------------- dynamic conv out ----------------
__global__ __launch_bounds__(AHC) void convout_kernel(float* __restrict__ out)
{
    int t = threadIdx.x, s = blockIdx.x, b = blockIdx.y;
    int h = t >> 6;
    const float* lg = g_ck + ((size_t)(b*SS)+s)*CKN + h*KSC;
    float w[KSC]; float mx = -3e38f;
    #pragma unroll
    for (int k=0;k<KSC;k++){ w[k]=lg[k]; mx = fmaxf(mx, w[k]); }
    float sum = 0.f;
    #pragma unroll
    for (int k=0;k<KSC;k++){ w[k]=fexp(w[k]-mx); sum += w[k]; }
    float invs = 1.f/sum;
    float a = 0.f;
    #pragma unroll
    for (int k=0;k<KSC;k++){
        int sp = s + k - PADC;
        if (0<=sp && sp<SS)
            a = fmaf(g_co[((size_t)(b*SS)+sp)*AHC + t], w[k], a);
    }
    out[((size_t)(b*SS)+s)*(2*AHC) + AHC + t] = a*invs;
}

// ---------------- attention: tensor-core QK^T (3xtf32) + softmax chain + tf32 PV ----------------
// dyn smem: sc[16][1040] | qsm[16][68] | tdsmS[1024] | maskS[1024] | stage[8][16*20]
#define ATTN_SMEM ((AR*SCL + AR*68 + SS + SS + 8*320)*4)

__global__ __launch_bounds__(256) void attn_tc_kernel(
    const int* __restrict__ mask, const float* __restrict__ gammas,
    float* __restrict__ out)
{
    extern __shared__ float sm[];
    float* sc    = sm;                 // AR * SCL
    float* qsm   = sm + AR*SCL;        // AR * 68
    float* tdsmS = qsm + AR*68;        // SS
    float* maskS = tdsmS + SS;         // SS
    float* stage = maskS + SS;         // 8 * 320

    const int t = threadIdx.x, warp = t>>5, lane = t&31;
    const int i0 = blockIdx.x * AR;
    const int h  = blockIdx.y;
    const int b  = blockIdx.z;

    // stage Q (pre-scaled by 1/8), mask, tdsm
    for (int e=t; e<AR*DC; e+=256){
        int r = e>>6, d = e&63;
        qsm[r*68+d] = g_mq[((size_t)(b*SS)+(i0+r))*AHC + h*DC + d] * 0.125f;
    }
    for (int e=t; e<SS; e+=256){
        maskS[e] = mask[b*SS+e] ? 1.f : 0.f;
        tdsmS[e] = g_tdsm[b*SS+e];
    }
    __syncthreads();

    // ---- phase 1: S = Qs @ K^T, 3xtf32 (fp32-grade precision) ----
    {
        const float* Kbase = g_mk + (size_t)(b*SS)*AHC + h*DC;
        FragA abig[8], asml[8];
        #pragma unroll
        for (int ks=0;ks<8;ks++){
            FragA araw;
            wmma::load_matrix_sync(araw, qsm + ks*8, 68);
            #pragma unroll
            for (int i=0;i<araw.num_elements;i++){
                float x  = araw.x[i];
                float bg = wmma::__float_to_tf32(x);
                abig[ks].x[i] = bg;
                asml[ks].x[i] = wmma::__float_to_tf32(x - bg);
            }
        }
        for (int nt = warp*8; nt < warp*8 + 8; nt++){
            FragC acc;
            wmma::fill_fragment(acc, 0.f);
            #pragma unroll
            for (int ks=0;ks<8;ks++){
                FragBc braw, bbig, bsml;
                wmma::load_matrix_sync(braw, Kbase + (size_t)(nt*16)*AHC + ks*8, AHC);
                #pragma unroll
                for (int i=0;i<braw.num_elements;i++){
                    float x  = braw.x[i];
                    float bg = wmma::__float_to_tf32(x);
                    bbig.x[i] = bg;
                    bsml.x[i] = wmma::__float_to_tf32(x - bg);
                }
                wmma::mma_sync(acc, abig[ks], bbig, acc);
                wmma::mma_sync(acc, abig[ks], bsml, acc);
                wmma::mma_sync(acc, asml[ks], bbig, acc);
            }
            wmma::store_matrix_sync(sc + nt*16, acc, SCL, wmma::mem_row_major);
        }
    }
    __syncthreads();

    // ---- phase 2: per-row softmax / cumsum / distance effect / softmax ----
    // lane owns strided keys j = c*32 + lane (conflict-free smem access)
    {
        float gv = gammas[h];
        float gm = -((gv > 20.f)? gv : log1pf(expf(gv)));
        for (int rr=0; rr<2; rr++){
            const int r = warp + rr*8;
            const int i = i0 + r;
            float* row = sc + r*SCL;

            float p[32];
            float lm = -3e38f;
            #pragma unroll
            for (int c=0;c<32;c++){
                int j = c*32 + lane;
                float sv = row[j];
                p[c] = sv;
                if (maskS[j] != 0.f) lm = fmaxf(lm, sv);
            }
            lm = warpMax(lm);
            float lsum = 0.f;
            #pragma unroll
            for (int c=0;c<32;c++){
                int j = c*32 + lane;
                float e = (maskS[j] != 0.f)? fexp(p[c]-lm) : 0.f;
                p[c] = e; lsum += e;
            }
            float Z = warpSum(lsum);
            float invZ = 1.f / Z;

            // ordered inclusive cumsum over j (stepwise warp scans)
            float off = 0.f;
            #pragma unroll
            for (int c=0;c<32;c++){
                float inc = p[c]*invZ;
                #pragma unroll
                for (int o=1;o<32;o<<=1){
                    float y = __shfl_up_sync(0xffffffffu, inc, o);
                    if (lane>=o) inc += y;
                }
                p[c] = off + inc;                    // inclusive cumsum at j
                off += __shfl_sync(0xffffffffu, inc, 31);
            }
            float T = off;

            float lm2 = -3e38f;
            #pragma unroll
            for (int c=0;c<32;c++){
                int j = c*32 + lane;
                float tail = T - p[c];
                float pos  = fabsf((float)(j - i));
                float ds   = fsqrt(tail*pos);
                float te   = fexp(gm*ds);
                te = fminf(fmaxf(te, 1e-5f), 1e5f);
                float eff  = te - ((j < i)? tdsmS[j] : 0.f);
                float v2   = row[j] * eff;
                p[c] = v2;
                if (maskS[j] != 0.f) lm2 = fmaxf(lm2, v2);
            }
            lm2 = warpMax(lm2);
            float ls2 = 0.f;
            #pragma unroll
            for (int c=0;c<32;c++){
                int j = c*32 + lane;
                float e = (maskS[j] != 0.f)? fexp(p[c]-lm2) : 0.f;
                p[c] = e; ls2 += e;
            }
            float Z2 = warpSum(ls2);
            float inv2 = 1.f / Z2;
            #pragma unroll
            for (int c=0;c<32;c++)
                row[c*32 + lane] = p[c]*inv2;
        }
    }
    __syncthreads();

    // ---- phase 3: ctx = P @ V, tf32; 4 n-tiles x 2 k-halves ----
    {
        const int ntile = warp & 3, khalf = warp >> 2;
        const float* Vbase = g_mv + (size_t)(b*SS)*AHC + h*DC + ntile*16;
        FragC acc;
        wmma::fill_fragment(acc, 0.f);
        for (int ks=0; ks<64; ks++){
            int k0 = khalf*512 + ks*8;
            FragA pf;
            wmma::load_matrix_sync(pf, sc + k0, SCL);
            cvtA(pf);
            FragB vf;
            wmma::load_matrix_sync(vf, Vbase + (size_t)k0*AHC, AHC);
            cvtB(vf);
            wmma::mma_sync(acc, pf, vf, acc);
        }
        wmma::store_matrix_sync(stage + warp*320, acc, 20, wmma::mem_row_major);
    }
    __syncthreads();
    for (int e=t; e<AR*DC; e+=256){
        int r = e>>6, d = e&63, nt = d>>4, c = d&15;
        float v = stage[nt*320 + r*20 + c] + stage[(4+nt)*320 + r*20 + c];
        out[((size_t)(b*SS)+(i0+r))*(2*AHC) + h*DC + d] = v;
    }
}

// ---------------- launch ----------------
extern "C" void kernel_launch(void* const* d_in, const int* in_sizes, int n_in,
                              void* d_out, int out_size)
{
    const float* Q     = (const float*)d_in[0];
    const float* Kin   = (const float*)d_in[1];
    const float* V     = (const float*)d_in[2];
    const float* td    = (const float*)d_in[3];
    const int*   mask  = (const int*)  d_in[4];
    const float* Wq    = (const float*)d_in[5];
    const float* Wk    = (const float*)d_in[6];
    const float* Wv    = (const float*)d_in[7];
    const float* dw_w  = (const float*)d_in[8];
    const float* pw_w  = (const float*)d_in[9];
    const float* sep_b = (const float*)d_in[10];
    const float* ck_W  = (const float*)d_in[11];
    const float* ck_b  = (const float*)d_in[12];
    const float* co_W  = (const float*)d_in[13];
    const float* co_b  = (const float*)d_in[14];
    const float* gam   = (const float*)d_in[15];
    float* out = (float*)d_out;

    cudaFuncSetAttribute(attn_tc_kernel,
                         cudaFuncAttributeMaxDynamicSharedMemorySize, ATTN_SMEM);

    dwconv_kernel<<<dim3(SS,BB), HIDC>>>(Kin, dw_w);

    dim3 gbig(AHC/BN, MM/BM, 5);
    big_gemm_tc<<<gbig, 256>>>(Q, Kin, V, Wq, Wk, Wv, co_W, co_b, pw_w, sep_b);

    dim3 gck(1, MM/BM);
    ck_gemm_tc<<<gck, 256>>>(ck_W, ck_b);

    tdsm_kernel<<<BB,256>>>(td, mask);
    convout_kernel<<<dim3(SS,BB), AHC>>>(out);
    attn_tc_kernel<<<dim3(SS/AR, HC, BB), 256, ATTN_SMEM>>>(mask, gam, out);
}

// round 12
// speedup vs baseline: 1.8765x; 1.0272x over previous
#include <cuda_runtime.h>
#include <mma.h>
#include <math.h>

using namespace nvcuda;

#define BB   4
#define SS   1024
#define HIDC 768
#define AHC  384
#define HC   6
#define DC   64
#define KSC  9
#define PADC 4
#define MM   (BB*SS)
#define CKN  (HC*KSC)   // 54
#define AR   16         // attention rows per block
#define SCL  1040       // score row leading dim

// ---------------- scratch ----------------
__device__ float g_mq [MM*AHC];
__device__ float g_mk [MM*AHC];
__device__ float g_mv [MM*AHC];
__device__ float g_mkc[MM*AHC];
__device__ float g_co [MM*AHC];
__device__ float g_dw [MM*HIDC];
__device__ float g_ck [MM*CKN];
__device__ float g_tdsm[MM];

// ---------------- fast math (FMA/ALU only, no MUFU) ----------------
__device__ __forceinline__ float fexp(float x){
    float z = x * 1.44269504f;
    z = fmaxf(z, -120.f);
    float zi = rintf(z);
    float f  = z - zi;
    float p  = 1.3333558e-3f;
    p = fmaf(p, f, 9.6181291e-3f);
    p = fmaf(p, f, 5.5504109e-2f);
    p = fmaf(p, f, 2.4022651e-1f);
    p = fmaf(p, f, 6.9314718e-1f);
    p = fmaf(p, f, 1.0f);
    int e = (int)zi;
    float s = __int_as_float((e + 127) << 23);
    return s * p;
}
__device__ __forceinline__ float fsqrt(float x){
    x = fmaxf(x, 1e-12f);
    float y = __int_as_float(0x5f3759dfu - (__float_as_int(x) >> 1));
    y = y * fmaf(-0.5f*x*y, y, 1.5f);
    y = y * fmaf(-0.5f*x*y, y, 1.5f);
    return x * y;
}

// ---------------- warp helpers ----------------
__device__ __forceinline__ float warpSum(float v){
    #pragma unroll
    for (int o=16;o;o>>=1) v += __shfl_xor_sync(0xffffffffu, v, o);
    return v;
}
__device__ __forceinline__ float warpMax(float v){
    #pragma unroll
    for (int o=16;o;o>>=1) v = fmaxf(v, __shfl_xor_sync(0xffffffffu, v, o));
    return v;
}
__device__ __forceinline__ float blockSum256(float v, float* red){
    v = warpSum(v);
    int w = threadIdx.x>>5, l = threadIdx.x&31;
    if (l==0) red[w]=v;
    __syncthreads();
    if (threadIdx.x<32){
        float x = (threadIdx.x<8)? red[threadIdx.x] : 0.f;
        x = warpSum(x);
        if (threadIdx.x==0) red[0]=x;
    }
    __syncthreads();
    float r = red[0];
    __syncthreads();
    return r;
}
__device__ __forceinline__ float blockMax256(float v, float* red){
    v = warpMax(v);
    int w = threadIdx.x>>5, l = threadIdx.x&31;
    if (l==0) red[w]=v;
    __syncthreads();
    if (threadIdx.x<32){
        float x = (threadIdx.x<8)? red[threadIdx.x] : -3e38f;
        x = warpMax(x);
        if (threadIdx.x==0) red[0]=x;
    }
    __syncthreads();
    float r = red[0];
    __syncthreads();
    return r;
}

// ================= WMMA tf32 GEMM =================
#define BM 128
#define BN 128
#define BK 16
#define LDA (BK+8)    // 24
#define LDB (BN+4)    // 132

typedef wmma::fragment<wmma::matrix_a, 16,16,8, wmma::precision::tf32, wmma::row_major> FragA;
typedef wmma::fragment<wmma::matrix_b, 16,16,8, wmma::precision::tf32, wmma::row_major> FragB;
typedef wmma::fragment<wmma::matrix_b, 16,16,8, wmma::precision::tf32, wmma::col_major> FragBc;
typedef wmma::fragment<wmma::accumulator, 16,16,8, float> FragC;

__device__ __forceinline__ void cvtA(FragA& f){
    #pragma unroll
    for (int i=0;i<f.num_elements;i++) f.x[i] = wmma::__float_to_tf32(f.x[i]);
}
__device__ __forceinline__ void cvtB(FragB& f){
    #pragma unroll
    for (int i=0;i<f.num_elements;i++) f.x[i] = wmma::__float_to_tf32(f.x[i]);
}

// ---------------- merged 5-way projection GEMM (wmma tf32) ----------------
__global__ __launch_bounds__(256) void big_gemm_tc(
   const float* __restrict__ Q, const float* __restrict__ Kin, const float* __restrict__ V,
   const float* __restrict__ Wq, const float* __restrict__ Wk, const float* __restrict__ Wv,
   const float* __restrict__ coW, const float* __restrict__ cob,
   const float* __restrict__ pww, const float* __restrict__ sepb)
{
    __shared__ __align__(16) float As[2][BM][LDA];
    __shared__ __align__(16) float Bs[2][BK][LDB];

    int z = blockIdx.z;
    const float* A; const float* B; float* C; const float* bias = nullptr; bool bt = false;
    switch (z){
      case 0: A=Q;    B=Wq;  C=g_mq;  break;
      case 1: A=Kin;  B=Wk;  C=g_mk;  break;
      case 2: A=V;    B=Wv;  C=g_mv;  break;
      case 3: A=V;    B=coW; C=g_co;  bias=cob;  break;
      default:A=g_dw; B=pww; C=g_mkc; bias=sepb; bt=true; break;
    }

    const int tid = threadIdx.x;
    const int warp = tid>>5;
    const int brow = blockIdx.y*BM, bcol = blockIdx.x*BN;
    const int wm = warp>>2, wn = warp&3;
    const int m0 = wm*64, n0 = wn*32;

    const int ar = tid>>2, ac = (tid&3)<<2;
    const int bk = tid>>4, bn = (tid&15)<<2;
    const int tn = tid>>2, tk = (tid&3)<<2;

    float4 pa0, pa1, pb0, pb1;

    auto ldtile = [&](int k0){
        pa0 = *(const float4*)(A + (size_t)(brow+ar   )*HIDC + k0 + ac);
        pa1 = *(const float4*)(A + (size_t)(brow+ar+64)*HIDC + k0 + ac);
        if (bt){
            pb0 = *(const float4*)(B + (size_t)(bcol+tn   )*HIDC + k0 + tk);
            pb1 = *(const float4*)(B + (size_t)(bcol+tn+64)*HIDC + k0 + tk);
        } else {
            pb0 = *(const float4*)(B + (size_t)(k0+bk)*AHC + bcol + bn);
            pb1 = *(const float4*)(B + (size_t)(k0+bk)*AHC + bcol + bn + 64);
        }
    };
    auto sttile = [&](int buf){
        *(float4*)&As[buf][ar   ][ac] = pa0;
        *(float4*)&As[buf][ar+64][ac] = pa1;
        if (bt){
            Bs[buf][tk+0][tn] = pb0.x; Bs[buf][tk+1][tn] = pb0.y;
            Bs[buf][tk+2][tn] = pb0.z; Bs[buf][tk+3][tn] = pb0.w;
            Bs[buf][tk+0][tn+64] = pb1.x; Bs[buf][tk+1][tn+64] = pb1.y;
            Bs[buf][tk+2][tn+64] = pb1.z; Bs[buf][tk+3][tn+64] = pb1.w;
        } else {
            *(float4*)&Bs[buf][bk][bn   ] = pb0;
            *(float4*)&Bs[buf][bk][bn+64] = pb1;
        }
    };

    FragC acc[4][2];
    #pragma unroll
    for (int mt=0;mt<4;mt++)
        #pragma unroll
        for (int nt=0;nt<2;nt++)
            wmma::fill_fragment(acc[mt][nt], 0.f);

    ldtile(0); sttile(0); __syncthreads();
    const int NT = HIDC/BK;
    int buf = 0;
    for (int t=0;t<NT;t++){
        if (t+1<NT) ldtile((t+1)*BK);
        #pragma unroll
        for (int ks=0;ks<2;ks++){
            FragA af[4]; FragB bf[2];
            #pragma unroll
            for (int mt=0;mt<4;mt++){
                wmma::load_matrix_sync(af[mt], &As[buf][m0+mt*16][ks*8], LDA);
                cvtA(af[mt]);
            }
            #pragma unroll
            for (int nt=0;nt<2;nt++){
                wmma::load_matrix_sync(bf[nt], &Bs[buf][ks*8][n0+nt*16], LDB);
                cvtB(bf[nt]);
            }
            #pragma unroll
            for (int mt=0;mt<4;mt++)
                #pragma unroll
                for (int nt=0;nt<2;nt++)
                    wmma::mma_sync(acc[mt][nt], af[mt], bf[nt], acc[mt][nt]);
        }
        if (t+1<NT){
            sttile(buf^1);
            __syncthreads();
            buf ^= 1;
        }
    }

    if (!bias){
        #pragma unroll
        for (int mt=0;mt<4;mt++)
            #pragma unroll
            for (int nt=0;nt<2;nt++)
                wmma::store_matrix_sync(
                    C + (size_t)(brow+m0+mt*16)*AHC + bcol + n0 + nt*16,
                    acc[mt][nt], AHC, wmma::mem_row_major);
    } else {
        __syncthreads();
        float* stage = &As[0][0][0] + warp*(16*20);
        const int lane = tid&31;
        #pragma unroll
        for (int mt=0;mt<4;mt++)
            #pragma unroll
            for (int nt=0;nt<2;nt++){
                wmma::store_matrix_sync(stage, acc[mt][nt], 20, wmma::mem_row_major);
                __syncwarp();
                #pragma unroll
                for (int e=lane; e<256; e+=32){
                    int r = e>>4, c = e&15;
                    int row = brow + m0 + mt*16 + r;
                    int col = bcol + n0 + nt*16 + c;
                    C[(size_t)row*AHC + col] = stage[r*20+c] + bias[col];
                }
                __syncwarp();
            }
    }
}

// ---------------- ck GEMM: (mkc*mq)[4096x384] @ ck_W[384x54] + ck_b ----------------
#define LDB2 68
__global__ __launch_bounds__(256) void ck_gemm_tc(
    const float* __restrict__ ckW, const float* __restrict__ ckb)
{
    __shared__ __align__(16) float As[2][BM][LDA];
    __shared__ __align__(16) float Bs[2][BK][LDB2];

    const float* A  = g_mkc;
    const float* A2 = g_mq;
    const int K = AHC, N = CKN;

    const int tid = threadIdx.x;
    const int warp = tid>>5;
    const int brow = blockIdx.y*BM;
    const int wm = warp>>1, wn = warp&1;
    const int m0 = wm*32, n0 = wn*32;

    const int ar = tid>>2, ac = (tid&3)<<2;
    const int bk = tid>>4, bcn = (tid&15)<<2;

    float4 pa0, pa1;
    float  pb[4];

    auto ldtile = [&](int k0){
        pa0 = *(const float4*)(A  + (size_t)(brow+ar   )*K + k0 + ac);
        float4 q0 = *(const float4*)(A2 + (size_t)(brow+ar   )*K + k0 + ac);
        pa0.x*=q0.x; pa0.y*=q0.y; pa0.z*=q0.z; pa0.w*=q0.w;
        pa1 = *(const float4*)(A  + (size_t)(brow+ar+64)*K + k0 + ac);
        float4 q1 = *(const float4*)(A2 + (size_t)(brow+ar+64)*K + k0 + ac);
        pa1.x*=q1.x; pa1.y*=q1.y; pa1.z*=q1.z; pa1.w*=q1.w;
        const float* bp = ckW + (size_t)(k0+bk)*N;
        #pragma unroll
        for (int e=0;e<4;e++){
            int c = bcn+e;
            pb[e] = (c<N)? bp[c] : 0.f;
        }
    };
    auto sttile = [&](int buf){
        *(float4*)&As[buf][ar   ][ac] = pa0;
        *(float4*)&As[buf][ar+64][ac] = pa1;
        #pragma unroll
        for (int e=0;e<4;e++) Bs[buf][bk][bcn+e] = pb[e];
    };

    FragC acc[2][2];
    #pragma unroll
    for (int mt=0;mt<2;mt++)
        #pragma unroll
        for (int nt=0;nt<2;nt++)
            wmma::fill_fragment(acc[mt][nt], 0.f);

    ldtile(0); sttile(0); __syncthreads();
    const int NT = K/BK;
    int buf = 0;
    for (int t=0;t<NT;t++){
        if (t+1<NT) ldtile((t+1)*BK);
        #pragma unroll
        for (int ks=0;ks<2;ks++){
            FragA af[2]; FragB bf[2];
            #pragma unroll
            for (int mt=0;mt<2;mt++){
                wmma::load_matrix_sync(af[mt], &As[buf][m0+mt*16][ks*8], LDA);
                cvtA(af[mt]);
            }
            #pragma unroll
            for (int nt=0;nt<2;nt++){
                wmma::load_matrix_sync(bf[nt], &Bs[buf][ks*8][n0+nt*16], LDB2);
                cvtB(bf[nt]);
            }
            #pragma unroll
            for (int mt=0;mt<2;mt++)
                #pragma unroll
                for (int nt=0;nt<2;nt++)
                    wmma::mma_sync(acc[mt][nt], af[mt], bf[nt], acc[mt][nt]);
        }
        if (t+1<NT){
            sttile(buf^1);
            __syncthreads();
            buf ^= 1;
        }
    }

    __syncthreads();
    float* stage = &As[0][0][0] + warp*(16*20);
    const int lane = tid&31;
    #pragma unroll
    for (int mt=0;mt<2;mt++)
        #pragma unroll
        for (int nt=0;nt<2;nt++){
            wmma::store_matrix_sync(stage, acc[mt][nt], 20, wmma::mem_row_major);
            __syncwarp();
            #pragma unroll
            for (int e=lane; e<256; e+=32){
                int r = e>>4, c = e&15;
                int row = brow + m0 + mt*16 + r;
                int col = n0 + nt*16 + c;
                if (col < N)
                    g_ck[(size_t)row*N + col] = stage[r*20+c] + ckb[col];
            }
            __syncwarp();
        }
}

// ---------------- depthwise conv: 8 positions per block, register sliding window ----------------
__global__ __launch_bounds__(HIDC) void dwconv_kernel(
    const float* __restrict__ Kin, const float* __restrict__ dww)
{
    const int c = threadIdx.x, s0 = blockIdx.x*8, b = blockIdx.y;
    float w[KSC];
    #pragma unroll
    for (int k=0;k<KSC;k++) w[k] = dww[c*KSC+k];
    float x[16];
    #pragma unroll
    for (int r=0;r<16;r++){
        int sp = s0 - PADC + r;
        x[r] = (0<=sp && sp<SS) ? Kin[((size_t)(b*SS)+sp)*HIDC + c] : 0.f;
    }
    #pragma unroll
    for (int q=0;q<8;q++){
        float acc = 0.f;
        #pragma unroll
        for (int k=0;k<KSC;k++) acc = fmaf(x[q+k], w[k], acc);
        g_dw[((size_t)(b*SS)+(s0+q))*HIDC + c] = acc;
    }
}

// ---------------- td softmax ----------------
__global__ __launch_bounds__(256) void tdsm_kernel(
    const float* __restrict__ td, const int* __restrict__ mask)
{
    __shared__ float red[9];
    int b = blockIdx.x, t = threadIdx.x;
    float ssum = 0.f;
    for (int j=t;j<SS;j+=256){ float x = td[b*SS+j]; ssum = fmaf(x,x,ssum); }
    float nrm = sqrtf(blockSum256(ssum, red));
    float inv = 1.f / fmaxf(nrm, 1e-12f);
    float lm = -3e38f;
    for (int j=t;j<SS;j+=256)
        if (mask[b*SS+j]) lm = fmaxf(lm, td[b*SS+j]*inv);
    float m = blockMax256(lm, red);
    float ls = 0.f;
    for (int j=t;j<SS;j+=256)
        if (mask[b*SS+j]) ls += expf(td[b*SS+j]*inv - m);
    float Z = blockSum256(ls, red);
    float iz = 1.f / Z;
    for (int j=t;j<SS;j+=256)
        g_tdsm[b*SS+j] = mask[b*SS+j] ? expf(td[b*SS+j]*inv - m)*iz : 0.f;
}

// ---------------- dynamic conv out: 8 positions per block ----------------
__global__ __launch_bounds__(AHC) void convout_kernel(float* __restrict__ out)
{
    __shared__ float cks[8][56];
    const int t = threadIdx.x, s0 = blockIdx.x*8, b = blockIdx.y;
    for (int e=t; e<8*CKN; e+=AHC){
        int q = e/CKN, c = e%CKN;
        cks[q][c] = g_ck[((size_t)(b*SS)+(s0+q))*CKN + c];
    }
    float x[16];
    #pragma unroll
    for (int r=0;r<16;r++){
        int sp = s0 - PADC + r;
        x[r] = (0<=sp && sp<SS) ? g_co[((size_t)(b*SS)+sp)*AHC + t] : 0.f;
    }
    __syncthreads();
    const int h = t >> 6;
    #pragma unroll
    for (int q=0;q<8;q++){
        float w[KSC]; float mx = -3e38f;
        #pragma unroll
        for (int k=0;k<KSC;k++){ w[k]=cks[q][h*KSC+k]; mx = fmaxf(mx, w[k]); }
        float sum = 0.f;
        #pragma unroll
        for (int k=0;k<KSC;k++){ w[k]=fexp(w[k]-mx); sum += w[k]; }
        float invs = 1.f/sum;
        float a = 0.f;
        #pragma unroll
        for (int k=0;k<KSC;k++) a = fmaf(x[q+k], w[k], a);
        out[((size_t)(b*SS)+(s0+q))*(2*AHC) + AHC + t] = a*invs;
    }
}

// ---------------- attention ----------------
// dyn smem: sc[16][1040] | maskS[1056] | tdsmS[1056] | scratch 8x1056 (aliased stage 8x320)
#define MJ(j) ((j) + ((j)>>5))
#define ATTN_SMEM ((AR*SCL + 1056 + 1056 + 8*1056)*4)

__global__ __launch_bounds__(256) void attn_tc_kernel(
    const int* __restrict__ mask, const float* __restrict__ gammas,
    float* __restrict__ out)
{
    extern __shared__ float sm[];
    float* sc      = sm;                   // AR * SCL
    float* maskS   = sm + AR*SCL;          // 1056 padded
    float* tdsmS   = maskS + 1056;         // 1056 padded
    float* scratch = tdsmS + 1056;         // 8 * 1056 (phase 2) / stage 8*320 (phase 3)

    const int t = threadIdx.x, warp = t>>5, lane = t&31;
    const int i0 = blockIdx.x * AR;
    const int h  = blockIdx.y;
    const int b  = blockIdx.z;

    for (int e=t; e<SS; e+=256){
        maskS[MJ(e)] = mask[b*SS+e] ? 1.f : 0.f;
        tdsmS[MJ(e)] = g_tdsm[b*SS+e];
    }
    __syncthreads();

    // ---- phase 1: S = Q @ K^T (unscaled; 1/8 folded into phase 2), 3xtf32 ----
    {
        const float* Qbase = g_mq + (size_t)(b*SS+i0)*AHC + h*DC;
        const float* Kbase = g_mk + (size_t)(b*SS)*AHC + h*DC;
        FragA abig[8], asml[8];
        #pragma unroll
        for (int ks=0;ks<8;ks++){
            FragA araw;
            wmma::load_matrix_sync(araw, Qbase + ks*8, AHC);
            #pragma unroll
            for (int i=0;i<araw.num_elements;i++){
                float x  = araw.x[i];
                float bg = wmma::__float_to_tf32(x);
                abig[ks].x[i] = bg;
                asml[ks].x[i] = wmma::__float_to_tf32(x - bg);
            }
        }
        for (int nt = warp*8; nt < warp*8 + 8; nt++){
            FragC acc;
            wmma::fill_fragment(acc, 0.f);
            #pragma unroll
            for (int ks=0;ks<8;ks++){
                FragBc braw, bbig, bsml;
                wmma::load_matrix_sync(braw, Kbase + (size_t)(nt*16)*AHC + ks*8, AHC);
                #pragma unroll
                for (int i=0;i<braw.num_elements;i++){
                    float x  = braw.x[i];
                    float bg = wmma::__float_to_tf32(x);
                    bbig.x[i] = bg;
                    bsml.x[i] = wmma::__float_to_tf32(x - bg);
                }
                wmma::mma_sync(acc, abig[ks], bbig, acc);
                wmma::mma_sync(acc, abig[ks], bsml, acc);
                wmma::mma_sync(acc, asml[ks], bbig, acc);
            }
            wmma::store_matrix_sync(sc + nt*16, acc, SCL, wmma::mem_row_major);
        }
    }
    __syncthreads();

    // ---- phase 2: softmax -> ordered cumsum (transpose trick) -> effect -> softmax ----
    {
        float gv = gammas[h];
        float gm = -((gv > 20.f)? gv : log1pf(expf(gv)));
        float* scr = scratch + warp*1056;

        for (int rr=0; rr<2; rr++){
            const int r = warp + rr*8;
            const int i = i0 + r;
            float* row = sc + r*SCL;

            // pass A (strided j = c*32+lane): softmax-1, write p_norm to scratch
            float lm = -3e38f;
            #pragma unroll
            for (int c=0;c<32;c++){
                int j = c*32 + lane;
                float sv = row[j]*0.125f;
                if (maskS[MJ(j)] != 0.f) lm = fmaxf(lm, sv);
            }
            lm = warpMax(lm);
            float p[32];
            float lsum = 0.f;
            #pragma unroll
            for (int c=0;c<32;c++){
                int j = c*32 + lane;
                float e = (maskS[MJ(j)] != 0.f)? fexp(row[j]*0.125f - lm) : 0.f;
                p[c] = e; lsum += e;
            }
            float Z = warpSum(lsum);
            float invZ = 1.f / Z;
            #pragma unroll
            for (int c=0;c<32;c++)
                scr[c*33 + lane] = p[c]*invZ;   // MJ(c*32+lane)
            __syncwarp();

            // pass B (consecutive j = lane*32+cc): serial prefix + ONE warp scan -> eff
            float q[32];
            float run = 0.f;
            #pragma unroll
            for (int cc=0;cc<32;cc++){
                run += scr[lane*33 + cc];       // MJ(lane*32+cc)
                q[cc] = run;
            }
            float xs = run;
            #pragma unroll
            for (int o=1;o<32;o<<=1){ float y=__shfl_up_sync(0xffffffffu,xs,o); if (lane>=o) xs+=y; }
            float T   = __shfl_sync(0xffffffffu, xs, 31);
            float off = xs - run;
            __syncwarp();
            #pragma unroll
            for (int cc=0;cc<32;cc++){
                int j = lane*32 + cc;
                float tail = T - (q[cc] + off);
                float pos  = fabsf((float)(j - i));
                float ds   = fsqrt(tail*pos);
                float te   = fexp(gm*ds);
                te = fminf(fmaxf(te, 1e-5f), 1e5f);
                float eff  = te - ((j < i)? tdsmS[MJ(j)] : 0.f);
                scr[lane*33 + cc] = eff;
            }
            __syncwarp();

            // pass C (strided): s2 = raw*eff, softmax-2, write probs
            float lm2 = -3e38f;
            #pragma unroll
            for (int c=0;c<32;c++){
                int j = c*32 + lane;
                float s2 = row[j]*0.125f * scr[c*33 + lane];
                p[c] = s2;
                if (maskS[MJ(j)] != 0.f) lm2 = fmaxf(lm2, s2);
            }
            lm2 = warpMax(lm2);
            float ls2 = 0.f;
            #pragma unroll
            for (int c=0;c<32;c++){
                int j = c*32 + lane;
                float e = (maskS[MJ(j)] != 0.f)? fexp(p[c]-lm2) : 0.f;
                p[c] = e; ls2 += e;
            }
            float Z2 = warpSum(ls2);
            float inv2 = 1.f / Z2;
            #pragma unroll
            for (int c=0;c<32;c++)
                row[c*32 + lane] = p[c]*inv2;
        }
    }
    __syncthreads();

    // ---- phase 3: ctx = P @ V, tf32; 4 n-tiles x 2 k-halves; stage aliases scratch ----
    {
        const int ntile = warp & 3, khalf = warp >> 2;
        const float* Vbase = g_mv + (size_t)(b*SS)*AHC + h*DC + ntile*16;
        FragC acc;
        wmma::fill_fragment(acc, 0.f);
        for (int ks=0; ks<64; ks++){
            int k0 = khalf*512 + ks*8;
            FragA pf;
            wmma::load_matrix_sync(pf, sc + k0, SCL);
            cvtA(pf);
            FragB vf;
            wmma::load_matrix_sync(vf, Vbase + (size_t)k0*AHC, AHC);
            cvtB(vf);
            wmma::mma_sync(acc, pf, vf, acc);
        }
        wmma::store_matrix_sync(scratch + warp*320, acc, 20, wmma::mem_row_major);
    }
    __syncthreads();
    for (int e=t; e<AR*DC; e+=256){
        int r = e>>6, d = e&63, nt = d>>4, c = d&15;
        float v = scratch[nt*320 + r*20 + c] + scratch[(4+nt)*320 + r*20 + c];
        out[((size_t)(b*SS)+(i0+r))*(2*AHC) + h*DC + d] = v;
    }
}

// ---------------- launch ----------------
extern "C" void kernel_launch(void* const* d_in, const int* in_sizes, int n_in,
                              void* d_out, int out_size)
{
    const float* Q     = (const float*)d_in[0];
    const float* Kin   = (const float*)d_in[1];
    const float* V     = (const float*)d_in[2];
    const float* td    = (const float*)d_in[3];
    const int*   mask  = (const int*)  d_in[4];
    const float* Wq    = (const float*)d_in[5];
    const float* Wk    = (const float*)d_in[6];
    const float* Wv    = (const float*)d_in[7];
    const float* dw_w  = (const float*)d_in[8];
    const float* pw_w  = (const float*)d_in[9];
    const float* sep_b = (const float*)d_in[10];
    const float* ck_W  = (const float*)d_in[11];
    const float* ck_b  = (const float*)d_in[12];
    const float* co_W  = (const float*)d_in[13];
    const float* co_b  = (const float*)d_in[14];
    const float* gam   = (const float*)d_in[15];
    float* out = (float*)d_out;

    cudaFuncSetAttribute(attn_tc_kernel,
                         cudaFuncAttributeMaxDynamicSharedMemorySize, ATTN_SMEM);

    dwconv_kernel<<<dim3(SS/8,BB), HIDC>>>(Kin, dw_w);

    dim3 gbig(AHC/BN, MM/BM, 5);
    big_gemm_tc<<<gbig, 256>>>(Q, Kin, V, Wq, Wk, Wv, co_W, co_b, pw_w, sep_b);

    dim3 gck(1, MM/BM);
    ck_gemm_tc<<<gck, 256>>>(ck_W, ck_b);

    tdsm_kernel<<<BB,256>>>(td, mask);
    convout_kernel<<<dim3(SS/8,BB), AHC>>>(out);
    attn_tc_kernel<<<dim3(SS/AR, HC, BB), 256, ATTN_SMEM>>>(mask, gam, out);
}